// round 15
// baseline (speedup 1.0000x reference)
#include <cuda_runtime.h>
#include <cuda_bf16.h>
#include <cuda_fp16.h>
#include <math.h>

#define Nn   100000
#define Ee   3200000
#define INC  500
#define KP1  512     // padded K for GEMM1
#define HIDC 256
#define OUTC 64
#define KHOP 10
#define NB_SCAN 98   // ceil(100000/1024)

// ---------------- scratch (static device globals; no allocation) ----------------
__device__ __align__(16) __nv_bfloat16 g_W1h[(size_t)HIDC * KP1];
__device__ __align__(16) __nv_bfloat16 g_W1l[(size_t)HIDC * KP1];
__device__ __align__(16) __nv_bfloat16 g_Hh[(size_t)Nn * HIDC];
__device__ __align__(16) __nv_bfloat16 g_Hl[(size_t)Nn * HIDC];
__device__ __align__(16) __nv_bfloat16 g_W2h[(size_t)OUTC * HIDC];
__device__ __align__(16) __nv_bfloat16 g_W2l[(size_t)OUTC * HIDC];
__device__ __align__(16) __half g_X[(size_t)(KHOP + 1) * Nn * OUTC];  // x_0..x_10
__device__ __align__(16) float g_dinv[Nn];
__device__ __align__(16) int   g_cnt[Nn];
__device__ __align__(16) int   g_rowptr[Nn + 2];
__device__ __align__(16) int   g_cursor[Nn];
__device__ __align__(16) int2  g_ew[Ee];                    // (src, w as half2(w,w))
__device__ __align__(16) int   g_bsums[NB_SCAN];
__device__ int g_is64;

// host-side stream/event objects, created once at static-init time.
struct HxStreams {
    cudaStream_t s2;
    cudaEvent_t  ev_fork, ev_join;
    HxStreams() {
        cudaStreamCreateWithFlags(&s2, cudaStreamNonBlocking);
        cudaEventCreateWithFlags(&ev_fork, cudaEventDisableTiming);
        cudaEventCreateWithFlags(&ev_join, cudaEventDisableTiming);
    }
};
static HxStreams g_hx;

// ---------------- edge dtype detection ----------------
__global__ void k_detect(const int* __restrict__ ei32) {
    int is64 = 1;
    for (int i = 1; i < 64; i += 2)
        if (ei32[i] != 0) { is64 = 0; break; }
    g_is64 = is64;
}

__device__ __forceinline__ void load_edge(const int* __restrict__ ei32, int e,
                                          int& r, int& c) {
    if (g_is64) {
        r = ei32[(size_t)2 * e];
        c = ei32[(size_t)2 * ((size_t)Ee + e)];
    } else {
        r = ei32[e];
        c = ei32[(size_t)Ee + e];
    }
    r = min(max(r, 0), Nn - 1);
    c = min(max(c, 0), Nn - 1);
}

// ---------------- degree / CSR construction ----------------
__global__ void k_zero_cnt() {
    int i = blockIdx.x * blockDim.x + threadIdx.x;
    if (i < Nn) g_cnt[i] = 0;
}

__global__ void k_count(const int* __restrict__ ei32) {
    int e = blockIdx.x * blockDim.x + threadIdx.x;
    if (e >= Ee) return;
    int r, c;
    load_edge(ei32, e, r, c);
    if (r != c) atomicAdd(&g_cnt[c], 1);
}

__global__ void k_scan1() {
    __shared__ int s[1024];
    int t = threadIdx.x;
    int i = blockIdx.x * 1024 + t;
    int v = (i < Nn) ? g_cnt[i] : 0;
    if (i < Nn) g_dinv[i] = rsqrtf((float)(v + 1));
    s[t] = v;
    __syncthreads();
    for (int o = 1; o < 1024; o <<= 1) {
        int y = (t >= o) ? s[t - o] : 0;
        __syncthreads();
        s[t] += y;
        __syncthreads();
    }
    int incl = s[t];
    if (i < Nn) g_rowptr[i] = incl - v;
    if (t == 1023) g_bsums[blockIdx.x] = incl;
}

__global__ void k_scan2() {
    int run = 0;
    for (int b = 0; b < NB_SCAN; b++) { int x = g_bsums[b]; g_bsums[b] = run; run += x; }
    g_rowptr[Nn] = run;
}

__global__ void k_scan3() {
    int i = blockIdx.x * 1024 + threadIdx.x;
    if (i < Nn) {
        int v = g_rowptr[i] + g_bsums[blockIdx.x];
        g_rowptr[i] = v;
        g_cursor[i] = v;
    }
}

__global__ void k_fill(const int* __restrict__ ei32) {
    int e = blockIdx.x * blockDim.x + threadIdx.x;
    if (e >= Ee) return;
    int r, c;
    load_edge(ei32, e, r, c);
    if (r != c) {
        int pos = atomicAdd(&g_cursor[c], 1);
        pos = min(max(pos, 0), Ee - 1);
        float w = g_dinv[r] * g_dinv[c];
        __half2 wh = __floats2half2_rn(w, w);
        g_ew[pos] = make_int2(r, (int)*reinterpret_cast<unsigned*>(&wh));
    }
}

// per-segment canonical order (warp bitonic on packed u64) for determinism
__global__ __launch_bounds__(256) void k_sortwarp() {
    int gw = (blockIdx.x * blockDim.x + threadIdx.x) >> 5;
    if (gw >= Nn) return;
    int lane = threadIdx.x & 31;
    int e0 = g_rowptr[gw], e1 = g_rowptr[gw + 1];
    int d = e1 - e0;
    if (d <= 1) return;

    if (d <= 64) {
        unsigned long long r0 = ~0ULL, r1 = ~0ULL;
        if (lane < d) {
            int2 q = g_ew[e0 + lane];
            r0 = ((unsigned long long)(unsigned)q.x << 32) | (unsigned)q.y;
        }
        if (lane + 32 < d) {
            int2 q = g_ew[e0 + lane + 32];
            r1 = ((unsigned long long)(unsigned)q.x << 32) | (unsigned)q.y;
        }
        const int v0 = lane, v1 = lane + 32;
        #pragma unroll
        for (int k = 2; k <= 64; k <<= 1) {
            #pragma unroll
            for (int j = k >> 1; j > 0; j >>= 1) {
                if (j == 32) {
                    unsigned long long lo = (r0 < r1) ? r0 : r1;
                    unsigned long long hi = (r0 < r1) ? r1 : r0;
                    r0 = lo; r1 = hi;
                } else {
                    {
                        unsigned long long p = __shfl_xor_sync(0xffffffffu, r0, j);
                        bool up = ((v0 & k) == 0);
                        bool lowr = ((v0 & j) == 0);
                        bool keepmin = (lowr == up);
                        r0 = keepmin ? ((r0 < p) ? r0 : p) : ((r0 > p) ? r0 : p);
                    }
                    {
                        unsigned long long p = __shfl_xor_sync(0xffffffffu, r1, j);
                        bool up = ((v1 & k) == 0);
                        bool lowr = ((v1 & j) == 0);
                        bool keepmin = (lowr == up);
                        r1 = keepmin ? ((r1 < p) ? r1 : p) : ((r1 > p) ? r1 : p);
                    }
                }
            }
        }
        if (lane < d)
            g_ew[e0 + lane] = make_int2((int)(r0 >> 32), (int)(unsigned)r0);
        if (lane + 32 < d)
            g_ew[e0 + lane + 32] = make_int2((int)(r1 >> 32), (int)(unsigned)r1);
    } else if (lane == 0) {
        for (int i = e0 + 1; i < e1; i++) {
            int2 cur = g_ew[i];
            int j = i - 1;
            while (j >= e0 && g_ew[j].x > cur.x) {
                g_ew[j + 1] = g_ew[j]; j--;
            }
            g_ew[j + 1] = cur;
        }
    }
}

// ---------------- weight conversions (tiny) ----------------
__global__ void k_convW1(const float* __restrict__ W) {
    int i = blockIdx.x * blockDim.x + threadIdx.x;
    if (i >= HIDC * KP1) return;
    int row = i >> 9, col = i & 511;
    float v = (col < INC) ? W[(size_t)row * INC + col] : 0.f;
    __nv_bfloat16 h = __float2bfloat16(v);
    g_W1h[i] = h;
    g_W1l[i] = __float2bfloat16(v - __bfloat162float(h));
}

__global__ void k_convW2(const float* __restrict__ W) {
    int i = blockIdx.x * blockDim.x + threadIdx.x;
    if (i >= OUTC * HIDC) return;
    float v = W[i];
    __nv_bfloat16 h = __float2bfloat16(v);
    g_W2h[i] = h;
    g_W2l[i] = __float2bfloat16(v - __bfloat162float(h));
}

// ---------------- mma / ldmatrix / cp.async primitives ----------------
__device__ __forceinline__ void mma16816(float c[4], const unsigned a[4], const unsigned b[2]) {
    asm volatile(
        "mma.sync.aligned.m16n8k16.row.col.f32.bf16.bf16.f32 "
        "{%0,%1,%2,%3}, {%4,%5,%6,%7}, {%8,%9}, {%0,%1,%2,%3};"
        : "+f"(c[0]), "+f"(c[1]), "+f"(c[2]), "+f"(c[3])
        : "r"(a[0]), "r"(a[1]), "r"(a[2]), "r"(a[3]), "r"(b[0]), "r"(b[1]));
}

__device__ __forceinline__ void ldsm4(unsigned r[4], const __nv_bfloat16* p) {
    unsigned a = (unsigned)__cvta_generic_to_shared(p);
    asm volatile("ldmatrix.sync.aligned.m8n8.x4.shared.b16 {%0,%1,%2,%3}, [%4];"
                 : "=r"(r[0]), "=r"(r[1]), "=r"(r[2]), "=r"(r[3]) : "r"(a));
}

__device__ __forceinline__ void cpa16(void* dst, const void* src, int bytes) {
    unsigned d = (unsigned)__cvta_generic_to_shared(dst);
    asm volatile("cp.async.cg.shared.global [%0], [%1], 16, %2;"
                 :: "r"(d), "l"(src), "r"(bytes));
}
__device__ __forceinline__ void cpa_commit() {
    asm volatile("cp.async.commit_group;");
}

// ---------------- GEMM1 with fused fp32 -> bf16 hi/lo split ----------------
#define ST  40
#define STF 36
__global__ __launch_bounds__(256)
void k_mma0(const float* __restrict__ Af, const float* __restrict__ bias, int M)
{
    constexpr int BN  = 128;
    constexpr int NS  = 8;
    constexpr int NIT = KP1 / 32;   // 16

    extern __shared__ __align__(16) char smem_raw[];
    __nv_bfloat16* sAh = reinterpret_cast<__nv_bfloat16*>(smem_raw);
    __nv_bfloat16* sAl = sAh + 2 * 128 * ST;
    __nv_bfloat16* sBh = sAl + 2 * 128 * ST;
    __nv_bfloat16* sBl = sBh + 2 * BN * ST;
    float*         sF  = reinterpret_cast<float*>(smem_raw + 4 * (2 * 128 * ST * 2));

    const int tid  = threadIdx.x;
    const int warp = tid >> 5;
    const int lane = tid & 31;
    const int grp  = lane >> 2;
    const int t4   = lane & 3;
    const int wm   = warp >> 1;
    const int wn   = warp & 1;
    const int m0   = blockIdx.x * 128;
    const int n0   = blockIdx.y * BN;

    float acc[2][NS][4];
    #pragma unroll
    for (int mi = 0; mi < 2; mi++)
        #pragma unroll
        for (int ni = 0; ni < NS; ni++)
            #pragma unroll
            for (int j = 0; j < 4; j++) acc[mi][ni][j] = 0.f;

    auto load_stage = [&](int it, int st) {
        int k0 = it * 32;
        #pragma unroll
        for (int i = 0; i < 4; i++) {
            int c   = tid + i * 256;
            int row = c >> 3, seg = c & 7;
            int gr  = m0 + row;
            int col = k0 + seg * 4;
            int nb  = (gr < M && col + 4 <= INC) ? 16 : 0;
            gr  = min(gr, M - 1);
            col = min(col, INC - 4);
            cpa16(&sF[row * STF + seg * 4], Af + (size_t)gr * INC + col, nb);
        }
        #pragma unroll
        for (int i = 0; i < 2; i++) {
            int c   = tid + i * 256;
            int row = c >> 2, seg = c & 3;
            size_t go = (size_t)(n0 + row) * KP1 + k0 + seg * 8;
            cpa16(&sBh[(st * BN + row) * ST + seg * 8], g_W1h + go, 16);
            cpa16(&sBl[(st * BN + row) * ST + seg * 8], g_W1l + go, 16);
        }
        cpa_commit();
    };

    load_stage(0, 0);

    const int tr = lane & 7;
    const int a_row_off = tr + ((lane >> 3) & 1) * 8;
    const int a_col_off = (lane >> 4) * 8;
    const int b_row_off = tr + (lane >> 4) * 8;
    const int b_col_off = ((lane >> 3) & 1) * 8;

    const int crow = tid >> 1, chalf = tid & 1;

    for (int it = 0; it < NIT; it++) {
        int st = it & 1;
        asm volatile("cp.async.wait_group 0;");
        __syncthreads();

        {
            const float* srcp = &sF[crow * STF + chalf * 16];
            __nv_bfloat16* dh = &sAh[(st * 128 + crow) * ST + chalf * 16];
            __nv_bfloat16* dl = &sAl[(st * 128 + crow) * ST + chalf * 16];
            #pragma unroll
            for (int j = 0; j < 4; j++) {
                float4 v = *reinterpret_cast<const float4*>(srcp + j * 4);
                __nv_bfloat16 h0 = __float2bfloat16(v.x);
                __nv_bfloat16 h1 = __float2bfloat16(v.y);
                __nv_bfloat16 h2 = __float2bfloat16(v.z);
                __nv_bfloat16 h3 = __float2bfloat16(v.w);
                __nv_bfloat16 l0 = __float2bfloat16(v.x - __bfloat162float(h0));
                __nv_bfloat16 l1 = __float2bfloat16(v.y - __bfloat162float(h1));
                __nv_bfloat16 l2 = __float2bfloat16(v.z - __bfloat162float(h2));
                __nv_bfloat16 l3 = __float2bfloat16(v.w - __bfloat162float(h3));
                __nv_bfloat162 hp0; hp0.x = h0; hp0.y = h1;
                __nv_bfloat162 hp1; hp1.x = h2; hp1.y = h3;
                __nv_bfloat162 lp0; lp0.x = l0; lp0.y = l1;
                __nv_bfloat162 lp1; lp1.x = l2; lp1.y = l3;
                uint2 hu, lu;
                hu.x = *reinterpret_cast<unsigned*>(&hp0);
                hu.y = *reinterpret_cast<unsigned*>(&hp1);
                lu.x = *reinterpret_cast<unsigned*>(&lp0);
                lu.y = *reinterpret_cast<unsigned*>(&lp1);
                *reinterpret_cast<uint2*>(dh + j * 4) = hu;
                *reinterpret_cast<uint2*>(dl + j * 4) = lu;
            }
        }
        __syncthreads();

        if (it + 1 < NIT) load_stage(it + 1, st ^ 1);

        #pragma unroll
        for (int ks = 0; ks < 2; ks++) {
            const int kk = ks * 16;
            unsigned ah[2][4], al[2][4];
            #pragma unroll
            for (int mi = 0; mi < 2; mi++) {
                int r = wm * 32 + mi * 16 + a_row_off;
                ldsm4(ah[mi], &sAh[(st * 128 + r) * ST + kk + a_col_off]);
                ldsm4(al[mi], &sAl[(st * 128 + r) * ST + kk + a_col_off]);
            }
            #pragma unroll
            for (int np = 0; np < NS / 2; np++) {
                int br = wn * 64 + np * 16 + b_row_off;
                unsigned bh[4], bl[4];
                ldsm4(bh, &sBh[(st * BN + br) * ST + kk + b_col_off]);
                ldsm4(bl, &sBl[(st * BN + br) * ST + kk + b_col_off]);
                mma16816(acc[0][2 * np    ], ah[0], bh + 0);
                mma16816(acc[1][2 * np    ], ah[1], bh + 0);
                mma16816(acc[0][2 * np + 1], ah[0], bh + 2);
                mma16816(acc[1][2 * np + 1], ah[1], bh + 2);
                mma16816(acc[0][2 * np    ], ah[0], bl + 0);
                mma16816(acc[1][2 * np    ], ah[1], bl + 0);
                mma16816(acc[0][2 * np + 1], ah[0], bl + 2);
                mma16816(acc[1][2 * np + 1], ah[1], bl + 2);
                mma16816(acc[0][2 * np    ], al[0], bh + 0);
                mma16816(acc[1][2 * np    ], al[1], bh + 0);
                mma16816(acc[0][2 * np + 1], al[0], bh + 2);
                mma16816(acc[1][2 * np + 1], al[1], bh + 2);
            }
        }
        __syncthreads();
    }

    #pragma unroll
    for (int mi = 0; mi < 2; mi++) {
        #pragma unroll
        for (int ni = 0; ni < NS; ni++) {
            int n = n0 + wn * 64 + ni * 8 + 2 * t4;
            float bb0 = bias[n], bb1 = bias[n + 1];
            #pragma unroll
            for (int half = 0; half < 2; half++) {
                int r = m0 + wm * 32 + mi * 16 + grp + half * 8;
                if (r >= M) continue;
                float v0 = fmaxf(acc[mi][ni][half * 2 + 0] + bb0, 0.f);
                float v1 = fmaxf(acc[mi][ni][half * 2 + 1] + bb1, 0.f);
                __nv_bfloat16 h0 = __float2bfloat16(v0);
                __nv_bfloat16 h1 = __float2bfloat16(v1);
                __nv_bfloat16 l0 = __float2bfloat16(v0 - __bfloat162float(h0));
                __nv_bfloat16 l1 = __float2bfloat16(v1 - __bfloat162float(h1));
                __nv_bfloat162 hp; hp.x = h0; hp.y = h1;
                __nv_bfloat162 lp; lp.x = l0; lp.y = l1;
                *reinterpret_cast<__nv_bfloat162*>(&g_Hh[(size_t)r * HIDC + n]) = hp;
                *reinterpret_cast<__nv_bfloat162*>(&g_Hl[(size_t)r * HIDC + n]) = lp;
            }
        }
    }
}

// ---------------- GEMM2 (bf16-split) ----------------
__global__ __launch_bounds__(256)
void k_mma1(const float* __restrict__ bias, int M)
{
    constexpr int BN  = 64;
    constexpr int Kd  = HIDC;
    constexpr int NS  = 4;
    constexpr int NIT = Kd / 32;

    extern __shared__ __align__(16) char smem_raw[];
    __nv_bfloat16* sAh = reinterpret_cast<__nv_bfloat16*>(smem_raw);
    __nv_bfloat16* sAl = sAh + 2 * 128 * ST;
    __nv_bfloat16* sBh = sAl + 2 * 128 * ST;
    __nv_bfloat16* sBl = sBh + 2 * BN * ST;

    const int tid  = threadIdx.x;
    const int warp = tid >> 5;
    const int lane = tid & 31;
    const int grp  = lane >> 2;
    const int t4   = lane & 3;
    const int wm   = warp >> 1;
    const int wn   = warp & 1;
    const int m0   = blockIdx.x * 128;

    float acc[2][NS][4];
    #pragma unroll
    for (int mi = 0; mi < 2; mi++)
        #pragma unroll
        for (int ni = 0; ni < NS; ni++)
            #pragma unroll
            for (int j = 0; j < 4; j++) acc[mi][ni][j] = 0.f;

    auto load_stage = [&](int it, int st) {
        int k0 = it * 32;
        #pragma unroll
        for (int i = 0; i < 2; i++) {
            int c   = tid + i * 256;
            int row = c >> 2, seg = c & 3;
            int gr  = m0 + row;
            int nb  = (gr < M) ? 16 : 0;
            gr = min(gr, M - 1);
            size_t go = (size_t)gr * Kd + k0 + seg * 8;
            cpa16(&sAh[(st * 128 + row) * ST + seg * 8], g_Hh + go, nb);
            cpa16(&sAl[(st * 128 + row) * ST + seg * 8], g_Hl + go, nb);
        }
        {
            int row = tid >> 2, seg = tid & 3;
            if (row < BN) {
                size_t go = (size_t)row * Kd + k0 + seg * 8;
                cpa16(&sBh[(st * BN + row) * ST + seg * 8], g_W2h + go, 16);
                cpa16(&sBl[(st * BN + row) * ST + seg * 8], g_W2l + go, 16);
            }
        }
        cpa_commit();
    };

    load_stage(0, 0);

    const int tr = lane & 7;
    const int a_row_off = tr + ((lane >> 3) & 1) * 8;
    const int a_col_off = (lane >> 4) * 8;
    const int b_row_off = tr + (lane >> 4) * 8;
    const int b_col_off = ((lane >> 3) & 1) * 8;

    for (int it = 0; it < NIT; it++) {
        int st = it & 1;
        if (it + 1 < NIT) {
            load_stage(it + 1, st ^ 1);
            asm volatile("cp.async.wait_group 1;");
        } else {
            asm volatile("cp.async.wait_group 0;");
        }
        __syncthreads();

        #pragma unroll
        for (int ks = 0; ks < 2; ks++) {
            const int kk = ks * 16;
            unsigned ah[2][4], al[2][4];
            #pragma unroll
            for (int mi = 0; mi < 2; mi++) {
                int r = wm * 32 + mi * 16 + a_row_off;
                ldsm4(ah[mi], &sAh[(st * 128 + r) * ST + kk + a_col_off]);
                ldsm4(al[mi], &sAl[(st * 128 + r) * ST + kk + a_col_off]);
            }
            #pragma unroll
            for (int np = 0; np < NS / 2; np++) {
                int br = wn * 32 + np * 16 + b_row_off;
                unsigned bh[4], bl[4];
                ldsm4(bh, &sBh[(st * BN + br) * ST + kk + b_col_off]);
                ldsm4(bl, &sBl[(st * BN + br) * ST + kk + b_col_off]);
                mma16816(acc[0][2 * np    ], ah[0], bh + 0);
                mma16816(acc[1][2 * np    ], ah[1], bh + 0);
                mma16816(acc[0][2 * np + 1], ah[0], bh + 2);
                mma16816(acc[1][2 * np + 1], ah[1], bh + 2);
                mma16816(acc[0][2 * np    ], ah[0], bl + 0);
                mma16816(acc[1][2 * np    ], ah[1], bl + 0);
                mma16816(acc[0][2 * np + 1], ah[0], bl + 2);
                mma16816(acc[1][2 * np + 1], ah[1], bl + 2);
                mma16816(acc[0][2 * np    ], al[0], bh + 0);
                mma16816(acc[1][2 * np    ], al[1], bh + 0);
                mma16816(acc[0][2 * np + 1], al[0], bh + 2);
                mma16816(acc[1][2 * np + 1], al[1], bh + 2);
            }
        }
        __syncthreads();
    }

    #pragma unroll
    for (int mi = 0; mi < 2; mi++) {
        #pragma unroll
        for (int ni = 0; ni < NS; ni++) {
            int n = wn * 32 + ni * 8 + 2 * t4;
            float bb0 = bias[n], bb1 = bias[n + 1];
            #pragma unroll
            for (int half = 0; half < 2; half++) {
                int r = m0 + wm * 32 + mi * 16 + grp + half * 8;
                if (r >= M) continue;
                float v0 = acc[mi][ni][half * 2 + 0] + bb0;
                float v1 = acc[mi][ni][half * 2 + 1] + bb1;
                *reinterpret_cast<__half2*>(&g_X[(size_t)r * OUTC + n]) =
                    __floats2half2_rn(v0, v1);
            }
        }
    }
}

// ---------------- propagation: x_k = Ahat x_{k-1}; hop==KHOP fuses combine ----------------
// Warp per node, 2 warps/CTA. lane = (group g = lane/8, slice s = lane%8).
// 16 edges/iter (4 independent LDG.128 gathers in flight). Weights half2(w,w),
// HFMA2 partials flushed to fp32 per iteration.
__global__ __launch_bounds__(64)
void k_prop(int hop, const float* __restrict__ pw, const float* __restrict__ pb,
            float* __restrict__ out)
{
    int gw = (blockIdx.x * blockDim.x + threadIdx.x) >> 5;
    if (gw >= Nn) return;
    const int lane = threadIdx.x & 31;
    const int g = lane >> 3;
    const int s = lane & 7;
    const uint4* xin = reinterpret_cast<const uint4*>(g_X + (size_t)(hop - 1) * Nn * OUTC);
    uint4*      xout = reinterpret_cast<uint4*>(g_X + (size_t)hop * Nn * OUTC);

    float acc[8];
    if (g == 0) {
        uint4 sv = xin[(size_t)gw * 8 + s];
        float2 sf0 = __half22float2(*reinterpret_cast<__half2*>(&sv.x));
        float2 sf1 = __half22float2(*reinterpret_cast<__half2*>(&sv.y));
        float2 sf2 = __half22float2(*reinterpret_cast<__half2*>(&sv.z));
        float2 sf3 = __half22float2(*reinterpret_cast<__half2*>(&sv.w));
        float d = g_dinv[gw];
        float sw = d * d;
        acc[0] = sw * sf0.x; acc[1] = sw * sf0.y;
        acc[2] = sw * sf1.x; acc[3] = sw * sf1.y;
        acc[4] = sw * sf2.x; acc[5] = sw * sf2.y;
        acc[6] = sw * sf3.x; acc[7] = sw * sf3.y;
    } else {
        #pragma unroll
        for (int j = 0; j < 8; j++) acc[j] = 0.f;
    }

    int e  = g_rowptr[gw];
    int e1 = g_rowptr[gw + 1];
    const __half2 hz = __floats2half2_rn(0.f, 0.f);

    // 16 edges/iter: 4 independent gathers per lane in flight
    for (; e + 16 <= e1; e += 16) {
        int2 qa = g_ew[e + g];
        int2 qb = g_ew[e + 4 + g];
        int2 qc = g_ew[e + 8 + g];
        int2 qd = g_ew[e + 12 + g];
        uint4 pa = xin[(size_t)qa.x * 8 + s];
        uint4 pb = xin[(size_t)qb.x * 8 + s];
        uint4 pc = xin[(size_t)qc.x * 8 + s];
        uint4 pd = xin[(size_t)qd.x * 8 + s];
        __half2 wa = *reinterpret_cast<__half2*>(&qa.y);
        __half2 wb = *reinterpret_cast<__half2*>(&qb.y);
        __half2 wc = *reinterpret_cast<__half2*>(&qc.y);
        __half2 wd = *reinterpret_cast<__half2*>(&qd.y);
        __half2 h0 = hz, h1 = hz, h2 = hz, h3 = hz;
        h0 = __hfma2(*reinterpret_cast<__half2*>(&pa.x), wa, h0);
        h1 = __hfma2(*reinterpret_cast<__half2*>(&pa.y), wa, h1);
        h2 = __hfma2(*reinterpret_cast<__half2*>(&pa.z), wa, h2);
        h3 = __hfma2(*reinterpret_cast<__half2*>(&pa.w), wa, h3);
        h0 = __hfma2(*reinterpret_cast<__half2*>(&pb.x), wb, h0);
        h1 = __hfma2(*reinterpret_cast<__half2*>(&pb.y), wb, h1);
        h2 = __hfma2(*reinterpret_cast<__half2*>(&pb.z), wb, h2);
        h3 = __hfma2(*reinterpret_cast<__half2*>(&pb.w), wb, h3);
        h0 = __hfma2(*reinterpret_cast<__half2*>(&pc.x), wc, h0);
        h1 = __hfma2(*reinterpret_cast<__half2*>(&pc.y), wc, h1);
        h2 = __hfma2(*reinterpret_cast<__half2*>(&pc.z), wc, h2);
        h3 = __hfma2(*reinterpret_cast<__half2*>(&pc.w), wc, h3);
        h0 = __hfma2(*reinterpret_cast<__half2*>(&pd.x), wd, h0);
        h1 = __hfma2(*reinterpret_cast<__half2*>(&pd.y), wd, h1);
        h2 = __hfma2(*reinterpret_cast<__half2*>(&pd.z), wd, h2);
        h3 = __hfma2(*reinterpret_cast<__half2*>(&pd.w), wd, h3);
        float2 f0 = __half22float2(h0);
        float2 f1 = __half22float2(h1);
        float2 f2 = __half22float2(h2);
        float2 f3 = __half22float2(h3);
        acc[0] += f0.x; acc[1] += f0.y;
        acc[2] += f1.x; acc[3] += f1.y;
        acc[4] += f2.x; acc[5] += f2.y;
        acc[6] += f3.x; acc[7] += f3.y;
    }
    // 8-edge step
    if (e + 8 <= e1) {
        int2 qa = g_ew[e + g];
        int2 qb = g_ew[e + 4 + g];
        uint4 pa = xin[(size_t)qa.x * 8 + s];
        uint4 pb = xin[(size_t)qb.x * 8 + s];
        __half2 wa = *reinterpret_cast<__half2*>(&qa.y);
        __half2 wb = *reinterpret_cast<__half2*>(&qb.y);
        __half2 h0 = hz, h1 = hz, h2 = hz, h3 = hz;
        h0 = __hfma2(*reinterpret_cast<__half2*>(&pa.x), wa, h0);
        h1 = __hfma2(*reinterpret_cast<__half2*>(&pa.y), wa, h1);
        h2 = __hfma2(*reinterpret_cast<__half2*>(&pa.z), wa, h2);
        h3 = __hfma2(*reinterpret_cast<__half2*>(&pa.w), wa, h3);
        h0 = __hfma2(*reinterpret_cast<__half2*>(&pb.x), wb, h0);
        h1 = __hfma2(*reinterpret_cast<__half2*>(&pb.y), wb, h1);
        h2 = __hfma2(*reinterpret_cast<__half2*>(&pb.z), wb, h2);
        h3 = __hfma2(*reinterpret_cast<__half2*>(&pb.w), wb, h3);
        float2 f0 = __half22float2(h0);
        float2 f1 = __half22float2(h1);
        float2 f2 = __half22float2(h2);
        float2 f3 = __half22float2(h3);
        acc[0] += f0.x; acc[1] += f0.y;
        acc[2] += f1.x; acc[3] += f1.y;
        acc[4] += f2.x; acc[5] += f2.y;
        acc[6] += f3.x; acc[7] += f3.y;
        e += 8;
    }
    // 4-edge tail, group-predicated
    for (; e < e1; e += 4) {
        int idx = e + g;
        __half2 h0 = hz, h1 = hz, h2 = hz, h3 = hz;
        if (idx < e1) {
            int2 q = g_ew[idx];
            uint4 p = xin[(size_t)q.x * 8 + s];
            __half2 w = *reinterpret_cast<__half2*>(&q.y);
            h0 = __hfma2(*reinterpret_cast<__half2*>(&p.x), w, h0);
            h1 = __hfma2(*reinterpret_cast<__half2*>(&p.y), w, h1);
            h2 = __hfma2(*reinterpret_cast<__half2*>(&p.z), w, h2);
            h3 = __hfma2(*reinterpret_cast<__half2*>(&p.w), w, h3);
        }
        float2 f0 = __half22float2(h0);
        float2 f1 = __half22float2(h1);
        float2 f2 = __half22float2(h2);
        float2 f3 = __half22float2(h3);
        acc[0] += f0.x; acc[1] += f0.y;
        acc[2] += f1.x; acc[3] += f1.y;
        acc[4] += f2.x; acc[5] += f2.y;
        acc[6] += f3.x; acc[7] += f3.y;
    }

    // merge the 4 group partials (all lanes end with the full slice values)
    #pragma unroll
    for (int j = 0; j < 8; j++) {
        acc[j] += __shfl_xor_sync(0xffffffffu, acc[j], 8);
        acc[j] += __shfl_xor_sync(0xffffffffu, acc[j], 16);
    }

    if (g == 0) {
        uint4 ov;
        __half2 o0 = __floats2half2_rn(acc[0], acc[1]);
        __half2 o1 = __floats2half2_rn(acc[2], acc[3]);
        __half2 o2 = __floats2half2_rn(acc[4], acc[5]);
        __half2 o3 = __floats2half2_rn(acc[6], acc[7]);
        ov.x = *reinterpret_cast<unsigned*>(&o0);
        ov.y = *reinterpret_cast<unsigned*>(&o1);
        ov.z = *reinterpret_cast<unsigned*>(&o2);
        ov.w = *reinterpret_cast<unsigned*>(&o3);
        xout[(size_t)gw * 8 + s] = ov;
    }

    // ---- fused final combine on the last hop ----
    if (hop == KHOP) {
        const float4* pw4 = reinterpret_cast<const float4*>(pw);
        float4 w0 = pw4[2 * s], w1 = pw4[2 * s + 1];
        const float bias = pb[0];
        float o[8];
        #pragma unroll
        for (int j = 0; j < 8; j++) o[j] = 0.f;

        // hops 0..KHOP-1 from history (broadcast loads across groups)
        for (int k = 0; k < KHOP; k++) {
            uint4 v = reinterpret_cast<const uint4*>(
                g_X + (size_t)k * Nn * OUTC)[(size_t)gw * 8 + s];
            float2 a0 = __half22float2(*reinterpret_cast<__half2*>(&v.x));
            float2 a1 = __half22float2(*reinterpret_cast<__half2*>(&v.y));
            float2 a2 = __half22float2(*reinterpret_cast<__half2*>(&v.z));
            float2 a3 = __half22float2(*reinterpret_cast<__half2*>(&v.w));
            float xk[8] = {a0.x, a0.y, a1.x, a1.y, a2.x, a2.y, a3.x, a3.y};
            float t = xk[0] * w0.x + xk[1] * w0.y + xk[2] * w0.z + xk[3] * w0.w
                    + xk[4] * w1.x + xk[5] * w1.y + xk[6] * w1.z + xk[7] * w1.w;
            t += __shfl_xor_sync(0xffffffffu, t, 1);
            t += __shfl_xor_sync(0xffffffffu, t, 2);
            t += __shfl_xor_sync(0xffffffffu, t, 4);
            float sk = 1.f / (1.f + expf(-(t + bias)));
            #pragma unroll
            for (int j = 0; j < 8; j++) o[j] = fmaf(sk, xk[j], o[j]);
        }
        // hop KHOP: x_10 must match what was stored (fp16-rounded), like k_comb read
        {
            float xk[8];
            xk[0] = __half2float(__floats2half2_rn(acc[0], acc[1]).x);
            xk[1] = __half2float(__floats2half2_rn(acc[0], acc[1]).y);
            xk[2] = __half2float(__floats2half2_rn(acc[2], acc[3]).x);
            xk[3] = __half2float(__floats2half2_rn(acc[2], acc[3]).y);
            xk[4] = __half2float(__floats2half2_rn(acc[4], acc[5]).x);
            xk[5] = __half2float(__floats2half2_rn(acc[4], acc[5]).y);
            xk[6] = __half2float(__floats2half2_rn(acc[6], acc[7]).x);
            xk[7] = __half2float(__floats2half2_rn(acc[6], acc[7]).y);
            float t = xk[0] * w0.x + xk[1] * w0.y + xk[2] * w0.z + xk[3] * w0.w
                    + xk[4] * w1.x + xk[5] * w1.y + xk[6] * w1.z + xk[7] * w1.w;
            t += __shfl_xor_sync(0xffffffffu, t, 1);
            t += __shfl_xor_sync(0xffffffffu, t, 2);
            t += __shfl_xor_sync(0xffffffffu, t, 4);
            float sk = 1.f / (1.f + expf(-(t + bias)));
            #pragma unroll
            for (int j = 0; j < 8; j++) o[j] = fmaf(sk, xk[j], o[j]);
        }
        if (g == 0) {
            float4* o4 = reinterpret_cast<float4*>(out + (size_t)gw * OUTC);
            o4[2 * s]     = make_float4(o[0], o[1], o[2], o[3]);
            o4[2 * s + 1] = make_float4(o[4], o[5], o[6], o[7]);
        }
    }
}

// ---------------- launch ----------------
extern "C" void kernel_launch(void* const* d_in, const int* in_sizes, int n_in,
                              void* d_out, int out_size)
{
    const float* node_feat = (const float*)d_in[0];
    const int*   ei32      = (const int*)d_in[1];
    const float* W1        = (const float*)d_in[2];
    const float* b1        = (const float*)d_in[3];
    const float* W2        = (const float*)d_in[4];
    const float* b2        = (const float*)d_in[5];
    const float* pw        = (const float*)d_in[6];
    const float* pb        = (const float*)d_in[7];
    float*       out       = (float*)d_out;

    const int TB = 256;
    int gN = (Nn + TB - 1) / TB;
    int gE = (Ee + TB - 1) / TB;
    int gW = (Nn * 32 + TB - 1) / TB;
    int gP = (Nn + 1) / 2;

    const int SMEM0 = 4 * 20480 + 128 * STF * 4;          // 100352 B
    const int SMEM1 = 2 * (2 * 128 + 2 * 64) * ST * 2;    // 61440 B
    cudaFuncSetAttribute(k_mma0, cudaFuncAttributeMaxDynamicSharedMemorySize, SMEM0);
    cudaFuncSetAttribute(k_mma1, cudaFuncAttributeMaxDynamicSharedMemorySize, SMEM1);

    // ---- fork: CSR chain on g_hx.s2, MLP chain on the default stream ----
    cudaEventRecord(g_hx.ev_fork, 0);
    cudaStreamWaitEvent(g_hx.s2, g_hx.ev_fork, 0);

    // CSR chain (stream s2)
    k_detect<<<1, 1, 0, g_hx.s2>>>(ei32);
    k_zero_cnt<<<gN, TB, 0, g_hx.s2>>>();
    k_count<<<gE, TB, 0, g_hx.s2>>>(ei32);
    k_scan1<<<NB_SCAN, 1024, 0, g_hx.s2>>>();
    k_scan2<<<1, 1, 0, g_hx.s2>>>();
    k_scan3<<<NB_SCAN, 1024, 0, g_hx.s2>>>();
    k_fill<<<gE, TB, 0, g_hx.s2>>>(ei32);
    k_sortwarp<<<gW, TB, 0, g_hx.s2>>>();
    cudaEventRecord(g_hx.ev_join, g_hx.s2);

    // MLP chain (default stream)
    k_convW1<<<(HIDC * KP1 + TB - 1) / TB, TB>>>(W1);
    k_convW2<<<(OUTC * HIDC + TB - 1) / TB, TB>>>(W2);
    dim3 g1((Nn + 127) / 128, 2);
    k_mma0<<<g1, 256, SMEM0>>>(node_feat, b1, Nn);
    dim3 g2((Nn + 127) / 128, 1);
    k_mma1<<<g2, 256, SMEM1>>>(b2, Nn);

    // ---- join: props need both x_0 (default stream) and CSR (s2) ----
    cudaStreamWaitEvent(0, g_hx.ev_join, 0);

    // SpMV hops; hop KHOP fuses the attention combine and writes out
    for (int k = 1; k <= KHOP; k++)
        k_prop<<<gP, 64>>>(k, pw, pb, out);
}

// round 16
// speedup vs baseline: 1.0461x; 1.0461x over previous
#include <cuda_runtime.h>
#include <cuda_bf16.h>
#include <cuda_fp16.h>
#include <math.h>

#define Nn   100000
#define Ee   3200000
#define INC  500
#define KP1  512     // padded K for GEMM1
#define HIDC 256
#define OUTC 64
#define KHOP 10
#define NB_SCAN 98   // ceil(100000/1024)

// ---------------- scratch (static device globals; no allocation) ----------------
__device__ __align__(16) __nv_bfloat16 g_W1h[(size_t)HIDC * KP1];
__device__ __align__(16) __nv_bfloat16 g_W1l[(size_t)HIDC * KP1];
__device__ __align__(16) __nv_bfloat16 g_Hh[(size_t)Nn * HIDC];
__device__ __align__(16) __nv_bfloat16 g_Hl[(size_t)Nn * HIDC];
__device__ __align__(16) __nv_bfloat16 g_W2h[(size_t)OUTC * HIDC];
__device__ __align__(16) __nv_bfloat16 g_W2l[(size_t)OUTC * HIDC];
__device__ __align__(16) __half g_X[(size_t)(KHOP + 1) * Nn * OUTC];  // x_0..x_10
__device__ __align__(16) float g_dinv[Nn];
__device__ __align__(16) int   g_cnt[Nn];
__device__ __align__(16) int   g_rowptr[Nn + 2];
__device__ __align__(16) int   g_cursor[Nn];
__device__ __align__(16) int2  g_ew[Ee];                    // (src, w as half2(w,w))
__device__ __align__(16) int   g_bsums[NB_SCAN];
__device__ int g_is64;

// host-side stream/event objects, created once at static-init time.
struct HxStreams {
    cudaStream_t s2;
    cudaEvent_t  ev_fork, ev_join;
    HxStreams() {
        cudaStreamCreateWithFlags(&s2, cudaStreamNonBlocking);
        cudaEventCreateWithFlags(&ev_fork, cudaEventDisableTiming);
        cudaEventCreateWithFlags(&ev_join, cudaEventDisableTiming);
    }
};
static HxStreams g_hx;

// ---------------- edge dtype detection ----------------
__global__ void k_detect(const int* __restrict__ ei32) {
    int is64 = 1;
    for (int i = 1; i < 64; i += 2)
        if (ei32[i] != 0) { is64 = 0; break; }
    g_is64 = is64;
}

__device__ __forceinline__ void load_edge(const int* __restrict__ ei32, int e,
                                          int& r, int& c) {
    if (g_is64) {
        r = ei32[(size_t)2 * e];
        c = ei32[(size_t)2 * ((size_t)Ee + e)];
    } else {
        r = ei32[e];
        c = ei32[(size_t)Ee + e];
    }
    r = min(max(r, 0), Nn - 1);
    c = min(max(c, 0), Nn - 1);
}

// ---------------- degree / CSR construction ----------------
__global__ void k_zero_cnt() {
    int i = blockIdx.x * blockDim.x + threadIdx.x;
    if (i < Nn) g_cnt[i] = 0;
}

__global__ void k_count(const int* __restrict__ ei32) {
    int e = blockIdx.x * blockDim.x + threadIdx.x;
    if (e >= Ee) return;
    int r, c;
    load_edge(ei32, e, r, c);
    if (r != c) atomicAdd(&g_cnt[c], 1);
}

__global__ void k_scan1() {
    __shared__ int s[1024];
    int t = threadIdx.x;
    int i = blockIdx.x * 1024 + t;
    int v = (i < Nn) ? g_cnt[i] : 0;
    if (i < Nn) g_dinv[i] = rsqrtf((float)(v + 1));
    s[t] = v;
    __syncthreads();
    for (int o = 1; o < 1024; o <<= 1) {
        int y = (t >= o) ? s[t - o] : 0;
        __syncthreads();
        s[t] += y;
        __syncthreads();
    }
    int incl = s[t];
    if (i < Nn) g_rowptr[i] = incl - v;
    if (t == 1023) g_bsums[blockIdx.x] = incl;
}

__global__ void k_scan2() {
    int run = 0;
    for (int b = 0; b < NB_SCAN; b++) { int x = g_bsums[b]; g_bsums[b] = run; run += x; }
    g_rowptr[Nn] = run;
}

__global__ void k_scan3() {
    int i = blockIdx.x * 1024 + threadIdx.x;
    if (i < Nn) {
        int v = g_rowptr[i] + g_bsums[blockIdx.x];
        g_rowptr[i] = v;
        g_cursor[i] = v;
    }
}

__global__ void k_fill(const int* __restrict__ ei32) {
    int e = blockIdx.x * blockDim.x + threadIdx.x;
    if (e >= Ee) return;
    int r, c;
    load_edge(ei32, e, r, c);
    if (r != c) {
        int pos = atomicAdd(&g_cursor[c], 1);
        pos = min(max(pos, 0), Ee - 1);
        float w = g_dinv[r] * g_dinv[c];
        __half2 wh = __floats2half2_rn(w, w);
        g_ew[pos] = make_int2(r, (int)*reinterpret_cast<unsigned*>(&wh));
    }
}

// per-segment canonical order (warp bitonic on packed u64) for determinism
__global__ __launch_bounds__(256) void k_sortwarp() {
    int gw = (blockIdx.x * blockDim.x + threadIdx.x) >> 5;
    if (gw >= Nn) return;
    int lane = threadIdx.x & 31;
    int e0 = g_rowptr[gw], e1 = g_rowptr[gw + 1];
    int d = e1 - e0;
    if (d <= 1) return;

    if (d <= 64) {
        unsigned long long r0 = ~0ULL, r1 = ~0ULL;
        if (lane < d) {
            int2 q = g_ew[e0 + lane];
            r0 = ((unsigned long long)(unsigned)q.x << 32) | (unsigned)q.y;
        }
        if (lane + 32 < d) {
            int2 q = g_ew[e0 + lane + 32];
            r1 = ((unsigned long long)(unsigned)q.x << 32) | (unsigned)q.y;
        }
        const int v0 = lane, v1 = lane + 32;
        #pragma unroll
        for (int k = 2; k <= 64; k <<= 1) {
            #pragma unroll
            for (int j = k >> 1; j > 0; j >>= 1) {
                if (j == 32) {
                    unsigned long long lo = (r0 < r1) ? r0 : r1;
                    unsigned long long hi = (r0 < r1) ? r1 : r0;
                    r0 = lo; r1 = hi;
                } else {
                    {
                        unsigned long long p = __shfl_xor_sync(0xffffffffu, r0, j);
                        bool up = ((v0 & k) == 0);
                        bool lowr = ((v0 & j) == 0);
                        bool keepmin = (lowr == up);
                        r0 = keepmin ? ((r0 < p) ? r0 : p) : ((r0 > p) ? r0 : p);
                    }
                    {
                        unsigned long long p = __shfl_xor_sync(0xffffffffu, r1, j);
                        bool up = ((v1 & k) == 0);
                        bool lowr = ((v1 & j) == 0);
                        bool keepmin = (lowr == up);
                        r1 = keepmin ? ((r1 < p) ? r1 : p) : ((r1 > p) ? r1 : p);
                    }
                }
            }
        }
        if (lane < d)
            g_ew[e0 + lane] = make_int2((int)(r0 >> 32), (int)(unsigned)r0);
        if (lane + 32 < d)
            g_ew[e0 + lane + 32] = make_int2((int)(r1 >> 32), (int)(unsigned)r1);
    } else if (lane == 0) {
        for (int i = e0 + 1; i < e1; i++) {
            int2 cur = g_ew[i];
            int j = i - 1;
            while (j >= e0 && g_ew[j].x > cur.x) {
                g_ew[j + 1] = g_ew[j]; j--;
            }
            g_ew[j + 1] = cur;
        }
    }
}

// ---------------- weight conversions (tiny) ----------------
__global__ void k_convW1(const float* __restrict__ W) {
    int i = blockIdx.x * blockDim.x + threadIdx.x;
    if (i >= HIDC * KP1) return;
    int row = i >> 9, col = i & 511;
    float v = (col < INC) ? W[(size_t)row * INC + col] : 0.f;
    __nv_bfloat16 h = __float2bfloat16(v);
    g_W1h[i] = h;
    g_W1l[i] = __float2bfloat16(v - __bfloat162float(h));
}

__global__ void k_convW2(const float* __restrict__ W) {
    int i = blockIdx.x * blockDim.x + threadIdx.x;
    if (i >= OUTC * HIDC) return;
    float v = W[i];
    __nv_bfloat16 h = __float2bfloat16(v);
    g_W2h[i] = h;
    g_W2l[i] = __float2bfloat16(v - __bfloat162float(h));
}

// ---------------- mma / ldmatrix / cp.async primitives ----------------
__device__ __forceinline__ void mma16816(float c[4], const unsigned a[4], const unsigned b[2]) {
    asm volatile(
        "mma.sync.aligned.m16n8k16.row.col.f32.bf16.bf16.f32 "
        "{%0,%1,%2,%3}, {%4,%5,%6,%7}, {%8,%9}, {%0,%1,%2,%3};"
        : "+f"(c[0]), "+f"(c[1]), "+f"(c[2]), "+f"(c[3])
        : "r"(a[0]), "r"(a[1]), "r"(a[2]), "r"(a[3]), "r"(b[0]), "r"(b[1]));
}

__device__ __forceinline__ void ldsm4(unsigned r[4], const __nv_bfloat16* p) {
    unsigned a = (unsigned)__cvta_generic_to_shared(p);
    asm volatile("ldmatrix.sync.aligned.m8n8.x4.shared.b16 {%0,%1,%2,%3}, [%4];"
                 : "=r"(r[0]), "=r"(r[1]), "=r"(r[2]), "=r"(r[3]) : "r"(a));
}

__device__ __forceinline__ void cpa16(void* dst, const void* src, int bytes) {
    unsigned d = (unsigned)__cvta_generic_to_shared(dst);
    asm volatile("cp.async.cg.shared.global [%0], [%1], 16, %2;"
                 :: "r"(d), "l"(src), "r"(bytes));
}
__device__ __forceinline__ void cpa_commit() {
    asm volatile("cp.async.commit_group;");
}

// ---------------- GEMM1 with fused fp32 -> bf16 hi/lo split ----------------
#define ST  40
#define STF 36
__global__ __launch_bounds__(256)
void k_mma0(const float* __restrict__ Af, const float* __restrict__ bias, int M)
{
    constexpr int BN  = 128;
    constexpr int NS  = 8;
    constexpr int NIT = KP1 / 32;   // 16

    extern __shared__ __align__(16) char smem_raw[];
    __nv_bfloat16* sAh = reinterpret_cast<__nv_bfloat16*>(smem_raw);
    __nv_bfloat16* sAl = sAh + 2 * 128 * ST;
    __nv_bfloat16* sBh = sAl + 2 * 128 * ST;
    __nv_bfloat16* sBl = sBh + 2 * BN * ST;
    float*         sF  = reinterpret_cast<float*>(smem_raw + 4 * (2 * 128 * ST * 2));

    const int tid  = threadIdx.x;
    const int warp = tid >> 5;
    const int lane = tid & 31;
    const int grp  = lane >> 2;
    const int t4   = lane & 3;
    const int wm   = warp >> 1;
    const int wn   = warp & 1;
    const int m0   = blockIdx.x * 128;
    const int n0   = blockIdx.y * BN;

    float acc[2][NS][4];
    #pragma unroll
    for (int mi = 0; mi < 2; mi++)
        #pragma unroll
        for (int ni = 0; ni < NS; ni++)
            #pragma unroll
            for (int j = 0; j < 4; j++) acc[mi][ni][j] = 0.f;

    auto load_stage = [&](int it, int st) {
        int k0 = it * 32;
        #pragma unroll
        for (int i = 0; i < 4; i++) {
            int c   = tid + i * 256;
            int row = c >> 3, seg = c & 7;
            int gr  = m0 + row;
            int col = k0 + seg * 4;
            int nb  = (gr < M && col + 4 <= INC) ? 16 : 0;
            gr  = min(gr, M - 1);
            col = min(col, INC - 4);
            cpa16(&sF[row * STF + seg * 4], Af + (size_t)gr * INC + col, nb);
        }
        #pragma unroll
        for (int i = 0; i < 2; i++) {
            int c   = tid + i * 256;
            int row = c >> 2, seg = c & 3;
            size_t go = (size_t)(n0 + row) * KP1 + k0 + seg * 8;
            cpa16(&sBh[(st * BN + row) * ST + seg * 8], g_W1h + go, 16);
            cpa16(&sBl[(st * BN + row) * ST + seg * 8], g_W1l + go, 16);
        }
        cpa_commit();
    };

    load_stage(0, 0);

    const int tr = lane & 7;
    const int a_row_off = tr + ((lane >> 3) & 1) * 8;
    const int a_col_off = (lane >> 4) * 8;
    const int b_row_off = tr + (lane >> 4) * 8;
    const int b_col_off = ((lane >> 3) & 1) * 8;

    const int crow = tid >> 1, chalf = tid & 1;

    for (int it = 0; it < NIT; it++) {
        int st = it & 1;
        asm volatile("cp.async.wait_group 0;");
        __syncthreads();

        {
            const float* srcp = &sF[crow * STF + chalf * 16];
            __nv_bfloat16* dh = &sAh[(st * 128 + crow) * ST + chalf * 16];
            __nv_bfloat16* dl = &sAl[(st * 128 + crow) * ST + chalf * 16];
            #pragma unroll
            for (int j = 0; j < 4; j++) {
                float4 v = *reinterpret_cast<const float4*>(srcp + j * 4);
                __nv_bfloat16 h0 = __float2bfloat16(v.x);
                __nv_bfloat16 h1 = __float2bfloat16(v.y);
                __nv_bfloat16 h2 = __float2bfloat16(v.z);
                __nv_bfloat16 h3 = __float2bfloat16(v.w);
                __nv_bfloat16 l0 = __float2bfloat16(v.x - __bfloat162float(h0));
                __nv_bfloat16 l1 = __float2bfloat16(v.y - __bfloat162float(h1));
                __nv_bfloat16 l2 = __float2bfloat16(v.z - __bfloat162float(h2));
                __nv_bfloat16 l3 = __float2bfloat16(v.w - __bfloat162float(h3));
                __nv_bfloat162 hp0; hp0.x = h0; hp0.y = h1;
                __nv_bfloat162 hp1; hp1.x = h2; hp1.y = h3;
                __nv_bfloat162 lp0; lp0.x = l0; lp0.y = l1;
                __nv_bfloat162 lp1; lp1.x = l2; lp1.y = l3;
                uint2 hu, lu;
                hu.x = *reinterpret_cast<unsigned*>(&hp0);
                hu.y = *reinterpret_cast<unsigned*>(&hp1);
                lu.x = *reinterpret_cast<unsigned*>(&lp0);
                lu.y = *reinterpret_cast<unsigned*>(&lp1);
                *reinterpret_cast<uint2*>(dh + j * 4) = hu;
                *reinterpret_cast<uint2*>(dl + j * 4) = lu;
            }
        }
        __syncthreads();

        if (it + 1 < NIT) load_stage(it + 1, st ^ 1);

        #pragma unroll
        for (int ks = 0; ks < 2; ks++) {
            const int kk = ks * 16;
            unsigned ah[2][4], al[2][4];
            #pragma unroll
            for (int mi = 0; mi < 2; mi++) {
                int r = wm * 32 + mi * 16 + a_row_off;
                ldsm4(ah[mi], &sAh[(st * 128 + r) * ST + kk + a_col_off]);
                ldsm4(al[mi], &sAl[(st * 128 + r) * ST + kk + a_col_off]);
            }
            #pragma unroll
            for (int np = 0; np < NS / 2; np++) {
                int br = wn * 64 + np * 16 + b_row_off;
                unsigned bh[4], bl[4];
                ldsm4(bh, &sBh[(st * BN + br) * ST + kk + b_col_off]);
                ldsm4(bl, &sBl[(st * BN + br) * ST + kk + b_col_off]);
                mma16816(acc[0][2 * np    ], ah[0], bh + 0);
                mma16816(acc[1][2 * np    ], ah[1], bh + 0);
                mma16816(acc[0][2 * np + 1], ah[0], bh + 2);
                mma16816(acc[1][2 * np + 1], ah[1], bh + 2);
                mma16816(acc[0][2 * np    ], ah[0], bl + 0);
                mma16816(acc[1][2 * np    ], ah[1], bl + 0);
                mma16816(acc[0][2 * np + 1], ah[0], bl + 2);
                mma16816(acc[1][2 * np + 1], ah[1], bl + 2);
                mma16816(acc[0][2 * np    ], al[0], bh + 0);
                mma16816(acc[1][2 * np    ], al[1], bh + 0);
                mma16816(acc[0][2 * np + 1], al[0], bh + 2);
                mma16816(acc[1][2 * np + 1], al[1], bh + 2);
            }
        }
        __syncthreads();
    }

    #pragma unroll
    for (int mi = 0; mi < 2; mi++) {
        #pragma unroll
        for (int ni = 0; ni < NS; ni++) {
            int n = n0 + wn * 64 + ni * 8 + 2 * t4;
            float bb0 = bias[n], bb1 = bias[n + 1];
            #pragma unroll
            for (int half = 0; half < 2; half++) {
                int r = m0 + wm * 32 + mi * 16 + grp + half * 8;
                if (r >= M) continue;
                float v0 = fmaxf(acc[mi][ni][half * 2 + 0] + bb0, 0.f);
                float v1 = fmaxf(acc[mi][ni][half * 2 + 1] + bb1, 0.f);
                __nv_bfloat16 h0 = __float2bfloat16(v0);
                __nv_bfloat16 h1 = __float2bfloat16(v1);
                __nv_bfloat16 l0 = __float2bfloat16(v0 - __bfloat162float(h0));
                __nv_bfloat16 l1 = __float2bfloat16(v1 - __bfloat162float(h1));
                __nv_bfloat162 hp; hp.x = h0; hp.y = h1;
                __nv_bfloat162 lp; lp.x = l0; lp.y = l1;
                *reinterpret_cast<__nv_bfloat162*>(&g_Hh[(size_t)r * HIDC + n]) = hp;
                *reinterpret_cast<__nv_bfloat162*>(&g_Hl[(size_t)r * HIDC + n]) = lp;
            }
        }
    }
}

// ---------------- GEMM2 (bf16-split) ----------------
__global__ __launch_bounds__(256)
void k_mma1(const float* __restrict__ bias, int M)
{
    constexpr int BN  = 64;
    constexpr int Kd  = HIDC;
    constexpr int NS  = 4;
    constexpr int NIT = Kd / 32;

    extern __shared__ __align__(16) char smem_raw[];
    __nv_bfloat16* sAh = reinterpret_cast<__nv_bfloat16*>(smem_raw);
    __nv_bfloat16* sAl = sAh + 2 * 128 * ST;
    __nv_bfloat16* sBh = sAl + 2 * 128 * ST;
    __nv_bfloat16* sBl = sBh + 2 * BN * ST;

    const int tid  = threadIdx.x;
    const int warp = tid >> 5;
    const int lane = tid & 31;
    const int grp  = lane >> 2;
    const int t4   = lane & 3;
    const int wm   = warp >> 1;
    const int wn   = warp & 1;
    const int m0   = blockIdx.x * 128;

    float acc[2][NS][4];
    #pragma unroll
    for (int mi = 0; mi < 2; mi++)
        #pragma unroll
        for (int ni = 0; ni < NS; ni++)
            #pragma unroll
            for (int j = 0; j < 4; j++) acc[mi][ni][j] = 0.f;

    auto load_stage = [&](int it, int st) {
        int k0 = it * 32;
        #pragma unroll
        for (int i = 0; i < 2; i++) {
            int c   = tid + i * 256;
            int row = c >> 2, seg = c & 3;
            int gr  = m0 + row;
            int nb  = (gr < M) ? 16 : 0;
            gr = min(gr, M - 1);
            size_t go = (size_t)gr * Kd + k0 + seg * 8;
            cpa16(&sAh[(st * 128 + row) * ST + seg * 8], g_Hh + go, nb);
            cpa16(&sAl[(st * 128 + row) * ST + seg * 8], g_Hl + go, nb);
        }
        {
            int row = tid >> 2, seg = tid & 3;
            if (row < BN) {
                size_t go = (size_t)row * Kd + k0 + seg * 8;
                cpa16(&sBh[(st * BN + row) * ST + seg * 8], g_W2h + go, 16);
                cpa16(&sBl[(st * BN + row) * ST + seg * 8], g_W2l + go, 16);
            }
        }
        cpa_commit();
    };

    load_stage(0, 0);

    const int tr = lane & 7;
    const int a_row_off = tr + ((lane >> 3) & 1) * 8;
    const int a_col_off = (lane >> 4) * 8;
    const int b_row_off = tr + (lane >> 4) * 8;
    const int b_col_off = ((lane >> 3) & 1) * 8;

    for (int it = 0; it < NIT; it++) {
        int st = it & 1;
        if (it + 1 < NIT) {
            load_stage(it + 1, st ^ 1);
            asm volatile("cp.async.wait_group 1;");
        } else {
            asm volatile("cp.async.wait_group 0;");
        }
        __syncthreads();

        #pragma unroll
        for (int ks = 0; ks < 2; ks++) {
            const int kk = ks * 16;
            unsigned ah[2][4], al[2][4];
            #pragma unroll
            for (int mi = 0; mi < 2; mi++) {
                int r = wm * 32 + mi * 16 + a_row_off;
                ldsm4(ah[mi], &sAh[(st * 128 + r) * ST + kk + a_col_off]);
                ldsm4(al[mi], &sAl[(st * 128 + r) * ST + kk + a_col_off]);
            }
            #pragma unroll
            for (int np = 0; np < NS / 2; np++) {
                int br = wn * 32 + np * 16 + b_row_off;
                unsigned bh[4], bl[4];
                ldsm4(bh, &sBh[(st * BN + br) * ST + kk + b_col_off]);
                ldsm4(bl, &sBl[(st * BN + br) * ST + kk + b_col_off]);
                mma16816(acc[0][2 * np    ], ah[0], bh + 0);
                mma16816(acc[1][2 * np    ], ah[1], bh + 0);
                mma16816(acc[0][2 * np + 1], ah[0], bh + 2);
                mma16816(acc[1][2 * np + 1], ah[1], bh + 2);
                mma16816(acc[0][2 * np    ], ah[0], bl + 0);
                mma16816(acc[1][2 * np    ], ah[1], bl + 0);
                mma16816(acc[0][2 * np + 1], ah[0], bl + 2);
                mma16816(acc[1][2 * np + 1], ah[1], bl + 2);
                mma16816(acc[0][2 * np    ], al[0], bh + 0);
                mma16816(acc[1][2 * np    ], al[1], bh + 0);
                mma16816(acc[0][2 * np + 1], al[0], bh + 2);
                mma16816(acc[1][2 * np + 1], al[1], bh + 2);
            }
        }
        __syncthreads();
    }

    #pragma unroll
    for (int mi = 0; mi < 2; mi++) {
        #pragma unroll
        for (int ni = 0; ni < NS; ni++) {
            int n = wn * 32 + ni * 8 + 2 * t4;
            float bb0 = bias[n], bb1 = bias[n + 1];
            #pragma unroll
            for (int half = 0; half < 2; half++) {
                int r = m0 + wm * 32 + mi * 16 + grp + half * 8;
                if (r >= M) continue;
                float v0 = acc[mi][ni][half * 2 + 0] + bb0;
                float v1 = acc[mi][ni][half * 2 + 1] + bb1;
                *reinterpret_cast<__half2*>(&g_X[(size_t)r * OUTC + n]) =
                    __floats2half2_rn(v0, v1);
            }
        }
    }
}

// ---------------- shared prop body (exact R14 8-wide loop) ----------------
__device__ __forceinline__ void prop_body(int gw, int lane, int g, int s,
                                          const uint4* __restrict__ xin,
                                          float acc[8])
{
    if (g == 0) {
        uint4 sv = xin[(size_t)gw * 8 + s];
        float2 sf0 = __half22float2(*reinterpret_cast<__half2*>(&sv.x));
        float2 sf1 = __half22float2(*reinterpret_cast<__half2*>(&sv.y));
        float2 sf2 = __half22float2(*reinterpret_cast<__half2*>(&sv.z));
        float2 sf3 = __half22float2(*reinterpret_cast<__half2*>(&sv.w));
        float d = g_dinv[gw];
        float sw = d * d;
        acc[0] = sw * sf0.x; acc[1] = sw * sf0.y;
        acc[2] = sw * sf1.x; acc[3] = sw * sf1.y;
        acc[4] = sw * sf2.x; acc[5] = sw * sf2.y;
        acc[6] = sw * sf3.x; acc[7] = sw * sf3.y;
    } else {
        #pragma unroll
        for (int j = 0; j < 8; j++) acc[j] = 0.f;
    }

    int e  = g_rowptr[gw];
    int e1 = g_rowptr[gw + 1];
    const __half2 hz = __floats2half2_rn(0.f, 0.f);

    for (; e + 8 <= e1; e += 8) {
        int2 qa = g_ew[e + g];
        int2 qb = g_ew[e + 4 + g];
        uint4 pa = xin[(size_t)qa.x * 8 + s];
        uint4 pb = xin[(size_t)qb.x * 8 + s];
        __half2 wa = *reinterpret_cast<__half2*>(&qa.y);
        __half2 wb = *reinterpret_cast<__half2*>(&qb.y);
        __half2 h0 = hz, h1 = hz, h2 = hz, h3 = hz;
        h0 = __hfma2(*reinterpret_cast<__half2*>(&pa.x), wa, h0);
        h1 = __hfma2(*reinterpret_cast<__half2*>(&pa.y), wa, h1);
        h2 = __hfma2(*reinterpret_cast<__half2*>(&pa.z), wa, h2);
        h3 = __hfma2(*reinterpret_cast<__half2*>(&pa.w), wa, h3);
        h0 = __hfma2(*reinterpret_cast<__half2*>(&pb.x), wb, h0);
        h1 = __hfma2(*reinterpret_cast<__half2*>(&pb.y), wb, h1);
        h2 = __hfma2(*reinterpret_cast<__half2*>(&pb.z), wb, h2);
        h3 = __hfma2(*reinterpret_cast<__half2*>(&pb.w), wb, h3);
        float2 f0 = __half22float2(h0);
        float2 f1 = __half22float2(h1);
        float2 f2 = __half22float2(h2);
        float2 f3 = __half22float2(h3);
        acc[0] += f0.x; acc[1] += f0.y;
        acc[2] += f1.x; acc[3] += f1.y;
        acc[4] += f2.x; acc[5] += f2.y;
        acc[6] += f3.x; acc[7] += f3.y;
    }
    for (; e < e1; e += 4) {
        int idx = e + g;
        __half2 h0 = hz, h1 = hz, h2 = hz, h3 = hz;
        if (idx < e1) {
            int2 q = g_ew[idx];
            uint4 p = xin[(size_t)q.x * 8 + s];
            __half2 w = *reinterpret_cast<__half2*>(&q.y);
            h0 = __hfma2(*reinterpret_cast<__half2*>(&p.x), w, h0);
            h1 = __hfma2(*reinterpret_cast<__half2*>(&p.y), w, h1);
            h2 = __hfma2(*reinterpret_cast<__half2*>(&p.z), w, h2);
            h3 = __hfma2(*reinterpret_cast<__half2*>(&p.w), w, h3);
        }
        float2 f0 = __half22float2(h0);
        float2 f1 = __half22float2(h1);
        float2 f2 = __half22float2(h2);
        float2 f3 = __half22float2(h3);
        acc[0] += f0.x; acc[1] += f0.y;
        acc[2] += f1.x; acc[3] += f1.y;
        acc[4] += f2.x; acc[5] += f2.y;
        acc[6] += f3.x; acc[7] += f3.y;
    }

    #pragma unroll
    for (int j = 0; j < 8; j++) {
        acc[j] += __shfl_xor_sync(0xffffffffu, acc[j], 8);
        acc[j] += __shfl_xor_sync(0xffffffffu, acc[j], 16);
    }
}

// hops 1..KHOP-1: pure SpMV (R14 register profile)
__global__ __launch_bounds__(64)
void k_prop(int hop)
{
    int gw = (blockIdx.x * blockDim.x + threadIdx.x) >> 5;
    if (gw >= Nn) return;
    const int lane = threadIdx.x & 31;
    const int g = lane >> 3;
    const int s = lane & 7;
    const uint4* xin = reinterpret_cast<const uint4*>(g_X + (size_t)(hop - 1) * Nn * OUTC);
    uint4*      xout = reinterpret_cast<uint4*>(g_X + (size_t)hop * Nn * OUTC);

    float acc[8];
    prop_body(gw, lane, g, s, xin, acc);

    if (g == 0) {
        uint4 ov;
        __half2 o0 = __floats2half2_rn(acc[0], acc[1]);
        __half2 o1 = __floats2half2_rn(acc[2], acc[3]);
        __half2 o2 = __floats2half2_rn(acc[4], acc[5]);
        __half2 o3 = __floats2half2_rn(acc[6], acc[7]);
        ov.x = *reinterpret_cast<unsigned*>(&o0);
        ov.y = *reinterpret_cast<unsigned*>(&o1);
        ov.z = *reinterpret_cast<unsigned*>(&o2);
        ov.w = *reinterpret_cast<unsigned*>(&o3);
        xout[(size_t)gw * 8 + s] = ov;
    }
}

// hop KHOP: SpMV + full attention combine (writes out; replaces k_comb)
__global__ __launch_bounds__(64)
void k_prop_last(const float* __restrict__ pw, const float* __restrict__ pb,
                 float* __restrict__ out)
{
    int gw = (blockIdx.x * blockDim.x + threadIdx.x) >> 5;
    if (gw >= Nn) return;
    const int lane = threadIdx.x & 31;
    const int g = lane >> 3;
    const int s = lane & 7;
    const uint4* xin = reinterpret_cast<const uint4*>(g_X + (size_t)(KHOP - 1) * Nn * OUTC);

    float acc[8];
    prop_body(gw, lane, g, s, xin, acc);

    const float4* pw4 = reinterpret_cast<const float4*>(pw);
    float4 w0 = pw4[2 * s], w1 = pw4[2 * s + 1];
    const float bias = pb[0];
    float o[8];
    #pragma unroll
    for (int j = 0; j < 8; j++) o[j] = 0.f;

    // hops 0..KHOP-1 from history
    for (int k = 0; k < KHOP; k++) {
        uint4 v = reinterpret_cast<const uint4*>(
            g_X + (size_t)k * Nn * OUTC)[(size_t)gw * 8 + s];
        float2 a0 = __half22float2(*reinterpret_cast<__half2*>(&v.x));
        float2 a1 = __half22float2(*reinterpret_cast<__half2*>(&v.y));
        float2 a2 = __half22float2(*reinterpret_cast<__half2*>(&v.z));
        float2 a3 = __half22float2(*reinterpret_cast<__half2*>(&v.w));
        float xk[8] = {a0.x, a0.y, a1.x, a1.y, a2.x, a2.y, a3.x, a3.y};
        float t = xk[0] * w0.x + xk[1] * w0.y + xk[2] * w0.z + xk[3] * w0.w
                + xk[4] * w1.x + xk[5] * w1.y + xk[6] * w1.z + xk[7] * w1.w;
        t += __shfl_xor_sync(0xffffffffu, t, 1);
        t += __shfl_xor_sync(0xffffffffu, t, 2);
        t += __shfl_xor_sync(0xffffffffu, t, 4);
        float sk = 1.f / (1.f + expf(-(t + bias)));
        #pragma unroll
        for (int j = 0; j < 8; j++) o[j] = fmaf(sk, xk[j], o[j]);
    }
    // hop KHOP from registers (fp16-rounded to match what k_comb would read)
    {
        __half2 r0 = __floats2half2_rn(acc[0], acc[1]);
        __half2 r1 = __floats2half2_rn(acc[2], acc[3]);
        __half2 r2 = __floats2half2_rn(acc[4], acc[5]);
        __half2 r3 = __floats2half2_rn(acc[6], acc[7]);
        float2 a0 = __half22float2(r0);
        float2 a1 = __half22float2(r1);
        float2 a2 = __half22float2(r2);
        float2 a3 = __half22float2(r3);
        float xk[8] = {a0.x, a0.y, a1.x, a1.y, a2.x, a2.y, a3.x, a3.y};
        float t = xk[0] * w0.x + xk[1] * w0.y + xk[2] * w0.z + xk[3] * w0.w
                + xk[4] * w1.x + xk[5] * w1.y + xk[6] * w1.z + xk[7] * w1.w;
        t += __shfl_xor_sync(0xffffffffu, t, 1);
        t += __shfl_xor_sync(0xffffffffu, t, 2);
        t += __shfl_xor_sync(0xffffffffu, t, 4);
        float sk = 1.f / (1.f + expf(-(t + bias)));
        #pragma unroll
        for (int j = 0; j < 8; j++) o[j] = fmaf(sk, xk[j], o[j]);
    }
    if (g == 0) {
        float4* o4 = reinterpret_cast<float4*>(out + (size_t)gw * OUTC);
        o4[2 * s]     = make_float4(o[0], o[1], o[2], o[3]);
        o4[2 * s + 1] = make_float4(o[4], o[5], o[6], o[7]);
    }
}

// ---------------- launch ----------------
extern "C" void kernel_launch(void* const* d_in, const int* in_sizes, int n_in,
                              void* d_out, int out_size)
{
    const float* node_feat = (const float*)d_in[0];
    const int*   ei32      = (const int*)d_in[1];
    const float* W1        = (const float*)d_in[2];
    const float* b1        = (const float*)d_in[3];
    const float* W2        = (const float*)d_in[4];
    const float* b2        = (const float*)d_in[5];
    const float* pw        = (const float*)d_in[6];
    const float* pb        = (const float*)d_in[7];
    float*       out       = (float*)d_out;

    const int TB = 256;
    int gN = (Nn + TB - 1) / TB;
    int gE = (Ee + TB - 1) / TB;
    int gW = (Nn * 32 + TB - 1) / TB;
    int gP = (Nn + 1) / 2;

    const int SMEM0 = 4 * 20480 + 128 * STF * 4;          // 100352 B
    const int SMEM1 = 2 * (2 * 128 + 2 * 64) * ST * 2;    // 61440 B
    cudaFuncSetAttribute(k_mma0, cudaFuncAttributeMaxDynamicSharedMemorySize, SMEM0);
    cudaFuncSetAttribute(k_mma1, cudaFuncAttributeMaxDynamicSharedMemorySize, SMEM1);

    // ---- fork: CSR chain on g_hx.s2, MLP chain on the default stream ----
    cudaEventRecord(g_hx.ev_fork, 0);
    cudaStreamWaitEvent(g_hx.s2, g_hx.ev_fork, 0);

    // CSR chain (stream s2)
    k_detect<<<1, 1, 0, g_hx.s2>>>(ei32);
    k_zero_cnt<<<gN, TB, 0, g_hx.s2>>>();
    k_count<<<gE, TB, 0, g_hx.s2>>>(ei32);
    k_scan1<<<NB_SCAN, 1024, 0, g_hx.s2>>>();
    k_scan2<<<1, 1, 0, g_hx.s2>>>();
    k_scan3<<<NB_SCAN, 1024, 0, g_hx.s2>>>();
    k_fill<<<gE, TB, 0, g_hx.s2>>>(ei32);
    k_sortwarp<<<gW, TB, 0, g_hx.s2>>>();
    cudaEventRecord(g_hx.ev_join, g_hx.s2);

    // MLP chain (default stream)
    k_convW1<<<(HIDC * KP1 + TB - 1) / TB, TB>>>(W1);
    k_convW2<<<(OUTC * HIDC + TB - 1) / TB, TB>>>(W2);
    dim3 g1((Nn + 127) / 128, 2);
    k_mma0<<<g1, 256, SMEM0>>>(node_feat, b1, Nn);
    dim3 g2((Nn + 127) / 128, 1);
    k_mma1<<<g2, 256, SMEM1>>>(b2, Nn);

    // ---- join: props need both x_0 (default stream) and CSR (s2) ----
    cudaStreamWaitEvent(0, g_hx.ev_join, 0);

    // hops 1..KHOP-1 pure SpMV, hop KHOP fused with attention combine
    for (int k = 1; k < KHOP; k++)
        k_prop<<<gP, 64>>>(k);
    k_prop_last<<<gP, 64>>>(pw, pb, out);
}

// round 17
// speedup vs baseline: 1.1162x; 1.0670x over previous
#include <cuda_runtime.h>
#include <cuda_bf16.h>
#include <cuda_fp16.h>
#include <math.h>

#define Nn   100000
#define Ee   3200000
#define INC  500
#define KP1  512     // padded K for GEMM1
#define HIDC 256
#define OUTC 64
#define KHOP 10
#define NB_SCAN 98   // ceil(100000/1024)

// ---------------- scratch (static device globals; no allocation) ----------------
__device__ __align__(16) __nv_bfloat16 g_W1h[(size_t)HIDC * KP1];
__device__ __align__(16) __nv_bfloat16 g_W1l[(size_t)HIDC * KP1];
__device__ __align__(16) __nv_bfloat16 g_Hh[(size_t)Nn * HIDC];
__device__ __align__(16) __nv_bfloat16 g_Hl[(size_t)Nn * HIDC];
__device__ __align__(16) __nv_bfloat16 g_W2h[(size_t)OUTC * HIDC];
__device__ __align__(16) __nv_bfloat16 g_W2l[(size_t)OUTC * HIDC];
__device__ __align__(16) __half g_X[(size_t)(KHOP + 1) * Nn * OUTC];  // x_0..x_10
__device__ __align__(16) float g_dinv[Nn];
__device__ __align__(16) int   g_cnt[Nn];
__device__ __align__(16) int   g_rowptr[Nn + 2];
__device__ __align__(16) int   g_cursor[Nn];
__device__ __align__(16) int2  g_ew[Ee];                    // (src, w as half2(w,w))
__device__ __align__(16) int   g_bsums[NB_SCAN];
__device__ int g_is64;

// host-side stream/event objects, created once at static-init time.
struct HxStreams {
    cudaStream_t s2;
    cudaEvent_t  ev_fork, ev_join;
    HxStreams() {
        cudaStreamCreateWithFlags(&s2, cudaStreamNonBlocking);
        cudaEventCreateWithFlags(&ev_fork, cudaEventDisableTiming);
        cudaEventCreateWithFlags(&ev_join, cudaEventDisableTiming);
    }
};
static HxStreams g_hx;

// ---------------- edge dtype detection ----------------
__global__ void k_detect(const int* __restrict__ ei32) {
    int is64 = 1;
    for (int i = 1; i < 64; i += 2)
        if (ei32[i] != 0) { is64 = 0; break; }
    g_is64 = is64;
}

__device__ __forceinline__ void load_edge(const int* __restrict__ ei32, int e,
                                          int& r, int& c) {
    if (g_is64) {
        r = ei32[(size_t)2 * e];
        c = ei32[(size_t)2 * ((size_t)Ee + e)];
    } else {
        r = ei32[e];
        c = ei32[(size_t)Ee + e];
    }
    r = min(max(r, 0), Nn - 1);
    c = min(max(c, 0), Nn - 1);
}

// ---------------- degree / CSR construction ----------------
__global__ void k_zero_cnt() {
    int i = blockIdx.x * blockDim.x + threadIdx.x;
    if (i < Nn) g_cnt[i] = 0;
}

__global__ void k_count(const int* __restrict__ ei32) {
    int e = blockIdx.x * blockDim.x + threadIdx.x;
    if (e >= Ee) return;
    int r, c;
    load_edge(ei32, e, r, c);
    if (r != c) atomicAdd(&g_cnt[c], 1);
}

__global__ void k_scan1() {
    __shared__ int s[1024];
    int t = threadIdx.x;
    int i = blockIdx.x * 1024 + t;
    int v = (i < Nn) ? g_cnt[i] : 0;
    if (i < Nn) g_dinv[i] = rsqrtf((float)(v + 1));
    s[t] = v;
    __syncthreads();
    for (int o = 1; o < 1024; o <<= 1) {
        int y = (t >= o) ? s[t - o] : 0;
        __syncthreads();
        s[t] += y;
        __syncthreads();
    }
    int incl = s[t];
    if (i < Nn) g_rowptr[i] = incl - v;
    if (t == 1023) g_bsums[blockIdx.x] = incl;
}

__global__ void k_scan2() {
    int run = 0;
    for (int b = 0; b < NB_SCAN; b++) { int x = g_bsums[b]; g_bsums[b] = run; run += x; }
    g_rowptr[Nn] = run;
}

__global__ void k_scan3() {
    int i = blockIdx.x * 1024 + threadIdx.x;
    if (i < Nn) {
        int v = g_rowptr[i] + g_bsums[blockIdx.x];
        g_rowptr[i] = v;
        g_cursor[i] = v;
    }
}

__global__ void k_fill(const int* __restrict__ ei32) {
    int e = blockIdx.x * blockDim.x + threadIdx.x;
    if (e >= Ee) return;
    int r, c;
    load_edge(ei32, e, r, c);
    if (r != c) {
        int pos = atomicAdd(&g_cursor[c], 1);
        pos = min(max(pos, 0), Ee - 1);
        float w = g_dinv[r] * g_dinv[c];
        __half2 wh = __floats2half2_rn(w, w);
        g_ew[pos] = make_int2(r, (int)*reinterpret_cast<unsigned*>(&wh));
    }
}

// per-segment canonical order (warp bitonic on packed u64) for determinism
__global__ __launch_bounds__(256) void k_sortwarp() {
    int gw = (blockIdx.x * blockDim.x + threadIdx.x) >> 5;
    if (gw >= Nn) return;
    int lane = threadIdx.x & 31;
    int e0 = g_rowptr[gw], e1 = g_rowptr[gw + 1];
    int d = e1 - e0;
    if (d <= 1) return;

    if (d <= 64) {
        unsigned long long r0 = ~0ULL, r1 = ~0ULL;
        if (lane < d) {
            int2 q = g_ew[e0 + lane];
            r0 = ((unsigned long long)(unsigned)q.x << 32) | (unsigned)q.y;
        }
        if (lane + 32 < d) {
            int2 q = g_ew[e0 + lane + 32];
            r1 = ((unsigned long long)(unsigned)q.x << 32) | (unsigned)q.y;
        }
        const int v0 = lane, v1 = lane + 32;
        #pragma unroll
        for (int k = 2; k <= 64; k <<= 1) {
            #pragma unroll
            for (int j = k >> 1; j > 0; j >>= 1) {
                if (j == 32) {
                    unsigned long long lo = (r0 < r1) ? r0 : r1;
                    unsigned long long hi = (r0 < r1) ? r1 : r0;
                    r0 = lo; r1 = hi;
                } else {
                    {
                        unsigned long long p = __shfl_xor_sync(0xffffffffu, r0, j);
                        bool up = ((v0 & k) == 0);
                        bool lowr = ((v0 & j) == 0);
                        bool keepmin = (lowr == up);
                        r0 = keepmin ? ((r0 < p) ? r0 : p) : ((r0 > p) ? r0 : p);
                    }
                    {
                        unsigned long long p = __shfl_xor_sync(0xffffffffu, r1, j);
                        bool up = ((v1 & k) == 0);
                        bool lowr = ((v1 & j) == 0);
                        bool keepmin = (lowr == up);
                        r1 = keepmin ? ((r1 < p) ? r1 : p) : ((r1 > p) ? r1 : p);
                    }
                }
            }
        }
        if (lane < d)
            g_ew[e0 + lane] = make_int2((int)(r0 >> 32), (int)(unsigned)r0);
        if (lane + 32 < d)
            g_ew[e0 + lane + 32] = make_int2((int)(r1 >> 32), (int)(unsigned)r1);
    } else if (lane == 0) {
        for (int i = e0 + 1; i < e1; i++) {
            int2 cur = g_ew[i];
            int j = i - 1;
            while (j >= e0 && g_ew[j].x > cur.x) {
                g_ew[j + 1] = g_ew[j]; j--;
            }
            g_ew[j + 1] = cur;
        }
    }
}

// ---------------- weight conversions (tiny) ----------------
__global__ void k_convW1(const float* __restrict__ W) {
    int i = blockIdx.x * blockDim.x + threadIdx.x;
    if (i >= HIDC * KP1) return;
    int row = i >> 9, col = i & 511;
    float v = (col < INC) ? W[(size_t)row * INC + col] : 0.f;
    __nv_bfloat16 h = __float2bfloat16(v);
    g_W1h[i] = h;
    g_W1l[i] = __float2bfloat16(v - __bfloat162float(h));
}

__global__ void k_convW2(const float* __restrict__ W) {
    int i = blockIdx.x * blockDim.x + threadIdx.x;
    if (i >= OUTC * HIDC) return;
    float v = W[i];
    __nv_bfloat16 h = __float2bfloat16(v);
    g_W2h[i] = h;
    g_W2l[i] = __float2bfloat16(v - __bfloat162float(h));
}

// ---------------- mma / ldmatrix / cp.async primitives ----------------
__device__ __forceinline__ void mma16816(float c[4], const unsigned a[4], const unsigned b[2]) {
    asm volatile(
        "mma.sync.aligned.m16n8k16.row.col.f32.bf16.bf16.f32 "
        "{%0,%1,%2,%3}, {%4,%5,%6,%7}, {%8,%9}, {%0,%1,%2,%3};"
        : "+f"(c[0]), "+f"(c[1]), "+f"(c[2]), "+f"(c[3])
        : "r"(a[0]), "r"(a[1]), "r"(a[2]), "r"(a[3]), "r"(b[0]), "r"(b[1]));
}

__device__ __forceinline__ void ldsm4(unsigned r[4], const __nv_bfloat16* p) {
    unsigned a = (unsigned)__cvta_generic_to_shared(p);
    asm volatile("ldmatrix.sync.aligned.m8n8.x4.shared.b16 {%0,%1,%2,%3}, [%4];"
                 : "=r"(r[0]), "=r"(r[1]), "=r"(r[2]), "=r"(r[3]) : "r"(a));
}

__device__ __forceinline__ void cpa16(void* dst, const void* src, int bytes) {
    unsigned d = (unsigned)__cvta_generic_to_shared(dst);
    asm volatile("cp.async.cg.shared.global [%0], [%1], 16, %2;"
                 :: "r"(d), "l"(src), "r"(bytes));
}
__device__ __forceinline__ void cpa_commit() {
    asm volatile("cp.async.commit_group;");
}

// ---------------- GEMM1 with fused fp32 -> bf16 hi/lo split ----------------
#define ST  40
#define STF 36
__global__ __launch_bounds__(256)
void k_mma0(const float* __restrict__ Af, const float* __restrict__ bias, int M)
{
    constexpr int BN  = 128;
    constexpr int NS  = 8;
    constexpr int NIT = KP1 / 32;   // 16

    extern __shared__ __align__(16) char smem_raw[];
    __nv_bfloat16* sAh = reinterpret_cast<__nv_bfloat16*>(smem_raw);
    __nv_bfloat16* sAl = sAh + 2 * 128 * ST;
    __nv_bfloat16* sBh = sAl + 2 * 128 * ST;
    __nv_bfloat16* sBl = sBh + 2 * BN * ST;
    float*         sF  = reinterpret_cast<float*>(smem_raw + 4 * (2 * 128 * ST * 2));

    const int tid  = threadIdx.x;
    const int warp = tid >> 5;
    const int lane = tid & 31;
    const int grp  = lane >> 2;
    const int t4   = lane & 3;
    const int wm   = warp >> 1;
    const int wn   = warp & 1;
    const int m0   = blockIdx.x * 128;
    const int n0   = blockIdx.y * BN;

    float acc[2][NS][4];
    #pragma unroll
    for (int mi = 0; mi < 2; mi++)
        #pragma unroll
        for (int ni = 0; ni < NS; ni++)
            #pragma unroll
            for (int j = 0; j < 4; j++) acc[mi][ni][j] = 0.f;

    auto load_stage = [&](int it, int st) {
        int k0 = it * 32;
        #pragma unroll
        for (int i = 0; i < 4; i++) {
            int c   = tid + i * 256;
            int row = c >> 3, seg = c & 7;
            int gr  = m0 + row;
            int col = k0 + seg * 4;
            int nb  = (gr < M && col + 4 <= INC) ? 16 : 0;
            gr  = min(gr, M - 1);
            col = min(col, INC - 4);
            cpa16(&sF[row * STF + seg * 4], Af + (size_t)gr * INC + col, nb);
        }
        #pragma unroll
        for (int i = 0; i < 2; i++) {
            int c   = tid + i * 256;
            int row = c >> 2, seg = c & 3;
            size_t go = (size_t)(n0 + row) * KP1 + k0 + seg * 8;
            cpa16(&sBh[(st * BN + row) * ST + seg * 8], g_W1h + go, 16);
            cpa16(&sBl[(st * BN + row) * ST + seg * 8], g_W1l + go, 16);
        }
        cpa_commit();
    };

    load_stage(0, 0);

    const int tr = lane & 7;
    const int a_row_off = tr + ((lane >> 3) & 1) * 8;
    const int a_col_off = (lane >> 4) * 8;
    const int b_row_off = tr + (lane >> 4) * 8;
    const int b_col_off = ((lane >> 3) & 1) * 8;

    const int crow = tid >> 1, chalf = tid & 1;

    for (int it = 0; it < NIT; it++) {
        int st = it & 1;
        asm volatile("cp.async.wait_group 0;");
        __syncthreads();

        {
            const float* srcp = &sF[crow * STF + chalf * 16];
            __nv_bfloat16* dh = &sAh[(st * 128 + crow) * ST + chalf * 16];
            __nv_bfloat16* dl = &sAl[(st * 128 + crow) * ST + chalf * 16];
            #pragma unroll
            for (int j = 0; j < 4; j++) {
                float4 v = *reinterpret_cast<const float4*>(srcp + j * 4);
                __nv_bfloat16 h0 = __float2bfloat16(v.x);
                __nv_bfloat16 h1 = __float2bfloat16(v.y);
                __nv_bfloat16 h2 = __float2bfloat16(v.z);
                __nv_bfloat16 h3 = __float2bfloat16(v.w);
                __nv_bfloat16 l0 = __float2bfloat16(v.x - __bfloat162float(h0));
                __nv_bfloat16 l1 = __float2bfloat16(v.y - __bfloat162float(h1));
                __nv_bfloat16 l2 = __float2bfloat16(v.z - __bfloat162float(h2));
                __nv_bfloat16 l3 = __float2bfloat16(v.w - __bfloat162float(h3));
                __nv_bfloat162 hp0; hp0.x = h0; hp0.y = h1;
                __nv_bfloat162 hp1; hp1.x = h2; hp1.y = h3;
                __nv_bfloat162 lp0; lp0.x = l0; lp0.y = l1;
                __nv_bfloat162 lp1; lp1.x = l2; lp1.y = l3;
                uint2 hu, lu;
                hu.x = *reinterpret_cast<unsigned*>(&hp0);
                hu.y = *reinterpret_cast<unsigned*>(&hp1);
                lu.x = *reinterpret_cast<unsigned*>(&lp0);
                lu.y = *reinterpret_cast<unsigned*>(&lp1);
                *reinterpret_cast<uint2*>(dh + j * 4) = hu;
                *reinterpret_cast<uint2*>(dl + j * 4) = lu;
            }
        }
        __syncthreads();

        if (it + 1 < NIT) load_stage(it + 1, st ^ 1);

        #pragma unroll
        for (int ks = 0; ks < 2; ks++) {
            const int kk = ks * 16;
            unsigned ah[2][4], al[2][4];
            #pragma unroll
            for (int mi = 0; mi < 2; mi++) {
                int r = wm * 32 + mi * 16 + a_row_off;
                ldsm4(ah[mi], &sAh[(st * 128 + r) * ST + kk + a_col_off]);
                ldsm4(al[mi], &sAl[(st * 128 + r) * ST + kk + a_col_off]);
            }
            #pragma unroll
            for (int np = 0; np < NS / 2; np++) {
                int br = wn * 64 + np * 16 + b_row_off;
                unsigned bh[4], bl[4];
                ldsm4(bh, &sBh[(st * BN + br) * ST + kk + b_col_off]);
                ldsm4(bl, &sBl[(st * BN + br) * ST + kk + b_col_off]);
                mma16816(acc[0][2 * np    ], ah[0], bh + 0);
                mma16816(acc[1][2 * np    ], ah[1], bh + 0);
                mma16816(acc[0][2 * np + 1], ah[0], bh + 2);
                mma16816(acc[1][2 * np + 1], ah[1], bh + 2);
                mma16816(acc[0][2 * np    ], ah[0], bl + 0);
                mma16816(acc[1][2 * np    ], ah[1], bl + 0);
                mma16816(acc[0][2 * np + 1], ah[0], bl + 2);
                mma16816(acc[1][2 * np + 1], ah[1], bl + 2);
                mma16816(acc[0][2 * np    ], al[0], bh + 0);
                mma16816(acc[1][2 * np    ], al[1], bh + 0);
                mma16816(acc[0][2 * np + 1], al[0], bh + 2);
                mma16816(acc[1][2 * np + 1], al[1], bh + 2);
            }
        }
        __syncthreads();
    }

    #pragma unroll
    for (int mi = 0; mi < 2; mi++) {
        #pragma unroll
        for (int ni = 0; ni < NS; ni++) {
            int n = n0 + wn * 64 + ni * 8 + 2 * t4;
            float bb0 = bias[n], bb1 = bias[n + 1];
            #pragma unroll
            for (int half = 0; half < 2; half++) {
                int r = m0 + wm * 32 + mi * 16 + grp + half * 8;
                if (r >= M) continue;
                float v0 = fmaxf(acc[mi][ni][half * 2 + 0] + bb0, 0.f);
                float v1 = fmaxf(acc[mi][ni][half * 2 + 1] + bb1, 0.f);
                __nv_bfloat16 h0 = __float2bfloat16(v0);
                __nv_bfloat16 h1 = __float2bfloat16(v1);
                __nv_bfloat16 l0 = __float2bfloat16(v0 - __bfloat162float(h0));
                __nv_bfloat16 l1 = __float2bfloat16(v1 - __bfloat162float(h1));
                __nv_bfloat162 hp; hp.x = h0; hp.y = h1;
                __nv_bfloat162 lp; lp.x = l0; lp.y = l1;
                *reinterpret_cast<__nv_bfloat162*>(&g_Hh[(size_t)r * HIDC + n]) = hp;
                *reinterpret_cast<__nv_bfloat162*>(&g_Hl[(size_t)r * HIDC + n]) = lp;
            }
        }
    }
}

// ---------------- GEMM2 (bf16-split) ----------------
__global__ __launch_bounds__(256)
void k_mma1(const float* __restrict__ bias, int M)
{
    constexpr int BN  = 64;
    constexpr int Kd  = HIDC;
    constexpr int NS  = 4;
    constexpr int NIT = Kd / 32;

    extern __shared__ __align__(16) char smem_raw[];
    __nv_bfloat16* sAh = reinterpret_cast<__nv_bfloat16*>(smem_raw);
    __nv_bfloat16* sAl = sAh + 2 * 128 * ST;
    __nv_bfloat16* sBh = sAl + 2 * 128 * ST;
    __nv_bfloat16* sBl = sBh + 2 * BN * ST;

    const int tid  = threadIdx.x;
    const int warp = tid >> 5;
    const int lane = tid & 31;
    const int grp  = lane >> 2;
    const int t4   = lane & 3;
    const int wm   = warp >> 1;
    const int wn   = warp & 1;
    const int m0   = blockIdx.x * 128;

    float acc[2][NS][4];
    #pragma unroll
    for (int mi = 0; mi < 2; mi++)
        #pragma unroll
        for (int ni = 0; ni < NS; ni++)
            #pragma unroll
            for (int j = 0; j < 4; j++) acc[mi][ni][j] = 0.f;

    auto load_stage = [&](int it, int st) {
        int k0 = it * 32;
        #pragma unroll
        for (int i = 0; i < 2; i++) {
            int c   = tid + i * 256;
            int row = c >> 2, seg = c & 3;
            int gr  = m0 + row;
            int nb  = (gr < M) ? 16 : 0;
            gr = min(gr, M - 1);
            size_t go = (size_t)gr * Kd + k0 + seg * 8;
            cpa16(&sAh[(st * 128 + row) * ST + seg * 8], g_Hh + go, nb);
            cpa16(&sAl[(st * 128 + row) * ST + seg * 8], g_Hl + go, nb);
        }
        {
            int row = tid >> 2, seg = tid & 3;
            if (row < BN) {
                size_t go = (size_t)row * Kd + k0 + seg * 8;
                cpa16(&sBh[(st * BN + row) * ST + seg * 8], g_W2h + go, 16);
                cpa16(&sBl[(st * BN + row) * ST + seg * 8], g_W2l + go, 16);
            }
        }
        cpa_commit();
    };

    load_stage(0, 0);

    const int tr = lane & 7;
    const int a_row_off = tr + ((lane >> 3) & 1) * 8;
    const int a_col_off = (lane >> 4) * 8;
    const int b_row_off = tr + (lane >> 4) * 8;
    const int b_col_off = ((lane >> 3) & 1) * 8;

    for (int it = 0; it < NIT; it++) {
        int st = it & 1;
        if (it + 1 < NIT) {
            load_stage(it + 1, st ^ 1);
            asm volatile("cp.async.wait_group 1;");
        } else {
            asm volatile("cp.async.wait_group 0;");
        }
        __syncthreads();

        #pragma unroll
        for (int ks = 0; ks < 2; ks++) {
            const int kk = ks * 16;
            unsigned ah[2][4], al[2][4];
            #pragma unroll
            for (int mi = 0; mi < 2; mi++) {
                int r = wm * 32 + mi * 16 + a_row_off;
                ldsm4(ah[mi], &sAh[(st * 128 + r) * ST + kk + a_col_off]);
                ldsm4(al[mi], &sAl[(st * 128 + r) * ST + kk + a_col_off]);
            }
            #pragma unroll
            for (int np = 0; np < NS / 2; np++) {
                int br = wn * 32 + np * 16 + b_row_off;
                unsigned bh[4], bl[4];
                ldsm4(bh, &sBh[(st * BN + br) * ST + kk + b_col_off]);
                ldsm4(bl, &sBl[(st * BN + br) * ST + kk + b_col_off]);
                mma16816(acc[0][2 * np    ], ah[0], bh + 0);
                mma16816(acc[1][2 * np    ], ah[1], bh + 0);
                mma16816(acc[0][2 * np + 1], ah[0], bh + 2);
                mma16816(acc[1][2 * np + 1], ah[1], bh + 2);
                mma16816(acc[0][2 * np    ], ah[0], bl + 0);
                mma16816(acc[1][2 * np    ], ah[1], bl + 0);
                mma16816(acc[0][2 * np + 1], ah[0], bl + 2);
                mma16816(acc[1][2 * np + 1], ah[1], bl + 2);
                mma16816(acc[0][2 * np    ], al[0], bh + 0);
                mma16816(acc[1][2 * np    ], al[1], bh + 0);
                mma16816(acc[0][2 * np + 1], al[0], bh + 2);
                mma16816(acc[1][2 * np + 1], al[1], bh + 2);
            }
        }
        __syncthreads();
    }

    #pragma unroll
    for (int mi = 0; mi < 2; mi++) {
        #pragma unroll
        for (int ni = 0; ni < NS; ni++) {
            int n = wn * 32 + ni * 8 + 2 * t4;
            float bb0 = bias[n], bb1 = bias[n + 1];
            #pragma unroll
            for (int half = 0; half < 2; half++) {
                int r = m0 + wm * 32 + mi * 16 + grp + half * 8;
                if (r >= M) continue;
                float v0 = acc[mi][ni][half * 2 + 0] + bb0;
                float v1 = acc[mi][ni][half * 2 + 1] + bb1;
                *reinterpret_cast<__half2*>(&g_X[(size_t)r * OUTC + n]) =
                    __floats2half2_rn(v0, v1);
            }
        }
    }
}

// ---------------- propagation: pure SpMV x_k = Ahat x_{k-1} ----------------
// Warp per node, 2 warps/CTA. lane = (group g = lane/8, slice s = lane%8).
// 8 edges/iter (R14 profile). Weights half2(w,w); HFMA2 partials flushed to
// fp32 each iteration.
__global__ __launch_bounds__(64)
void k_prop(int hop)
{
    int gw = (blockIdx.x * blockDim.x + threadIdx.x) >> 5;
    if (gw >= Nn) return;
    const int lane = threadIdx.x & 31;
    const int g = lane >> 3;
    const int s = lane & 7;
    const uint4* xin = reinterpret_cast<const uint4*>(g_X + (size_t)(hop - 1) * Nn * OUTC);
    uint4*      xout = reinterpret_cast<uint4*>(g_X + (size_t)hop * Nn * OUTC);

    float acc[8];
    if (g == 0) {
        uint4 sv = xin[(size_t)gw * 8 + s];
        float2 sf0 = __half22float2(*reinterpret_cast<__half2*>(&sv.x));
        float2 sf1 = __half22float2(*reinterpret_cast<__half2*>(&sv.y));
        float2 sf2 = __half22float2(*reinterpret_cast<__half2*>(&sv.z));
        float2 sf3 = __half22float2(*reinterpret_cast<__half2*>(&sv.w));
        float d = g_dinv[gw];
        float sw = d * d;
        acc[0] = sw * sf0.x; acc[1] = sw * sf0.y;
        acc[2] = sw * sf1.x; acc[3] = sw * sf1.y;
        acc[4] = sw * sf2.x; acc[5] = sw * sf2.y;
        acc[6] = sw * sf3.x; acc[7] = sw * sf3.y;
    } else {
        #pragma unroll
        for (int j = 0; j < 8; j++) acc[j] = 0.f;
    }

    int e  = g_rowptr[gw];
    int e1 = g_rowptr[gw + 1];
    const __half2 hz = __floats2half2_rn(0.f, 0.f);

    for (; e + 8 <= e1; e += 8) {
        int2 qa = g_ew[e + g];
        int2 qb = g_ew[e + 4 + g];
        uint4 pa = xin[(size_t)qa.x * 8 + s];
        uint4 pb = xin[(size_t)qb.x * 8 + s];
        __half2 wa = *reinterpret_cast<__half2*>(&qa.y);
        __half2 wb = *reinterpret_cast<__half2*>(&qb.y);
        __half2 h0 = hz, h1 = hz, h2 = hz, h3 = hz;
        h0 = __hfma2(*reinterpret_cast<__half2*>(&pa.x), wa, h0);
        h1 = __hfma2(*reinterpret_cast<__half2*>(&pa.y), wa, h1);
        h2 = __hfma2(*reinterpret_cast<__half2*>(&pa.z), wa, h2);
        h3 = __hfma2(*reinterpret_cast<__half2*>(&pa.w), wa, h3);
        h0 = __hfma2(*reinterpret_cast<__half2*>(&pb.x), wb, h0);
        h1 = __hfma2(*reinterpret_cast<__half2*>(&pb.y), wb, h1);
        h2 = __hfma2(*reinterpret_cast<__half2*>(&pb.z), wb, h2);
        h3 = __hfma2(*reinterpret_cast<__half2*>(&pb.w), wb, h3);
        float2 f0 = __half22float2(h0);
        float2 f1 = __half22float2(h1);
        float2 f2 = __half22float2(h2);
        float2 f3 = __half22float2(h3);
        acc[0] += f0.x; acc[1] += f0.y;
        acc[2] += f1.x; acc[3] += f1.y;
        acc[4] += f2.x; acc[5] += f2.y;
        acc[6] += f3.x; acc[7] += f3.y;
    }
    for (; e < e1; e += 4) {
        int idx = e + g;
        __half2 h0 = hz, h1 = hz, h2 = hz, h3 = hz;
        if (idx < e1) {
            int2 q = g_ew[idx];
            uint4 p = xin[(size_t)q.x * 8 + s];
            __half2 w = *reinterpret_cast<__half2*>(&q.y);
            h0 = __hfma2(*reinterpret_cast<__half2*>(&p.x), w, h0);
            h1 = __hfma2(*reinterpret_cast<__half2*>(&p.y), w, h1);
            h2 = __hfma2(*reinterpret_cast<__half2*>(&p.z), w, h2);
            h3 = __hfma2(*reinterpret_cast<__half2*>(&p.w), w, h3);
        }
        float2 f0 = __half22float2(h0);
        float2 f1 = __half22float2(h1);
        float2 f2 = __half22float2(h2);
        float2 f3 = __half22float2(h3);
        acc[0] += f0.x; acc[1] += f0.y;
        acc[2] += f1.x; acc[3] += f1.y;
        acc[4] += f2.x; acc[5] += f2.y;
        acc[6] += f3.x; acc[7] += f3.y;
    }

    #pragma unroll
    for (int j = 0; j < 8; j++) {
        acc[j] += __shfl_xor_sync(0xffffffffu, acc[j], 8);
        acc[j] += __shfl_xor_sync(0xffffffffu, acc[j], 16);
    }

    if (g == 0) {
        uint4 ov;
        __half2 o0 = __floats2half2_rn(acc[0], acc[1]);
        __half2 o1 = __floats2half2_rn(acc[2], acc[3]);
        __half2 o2 = __floats2half2_rn(acc[4], acc[5]);
        __half2 o3 = __floats2half2_rn(acc[6], acc[7]);
        ov.x = *reinterpret_cast<unsigned*>(&o0);
        ov.y = *reinterpret_cast<unsigned*>(&o1);
        ov.z = *reinterpret_cast<unsigned*>(&o2);
        ov.w = *reinterpret_cast<unsigned*>(&o3);
        xout[(size_t)gw * 8 + s] = ov;
    }
}

// ---------------- final combine: out = sum_k sigmoid(x_k . pw + pb) * x_k ----------------
__global__ __launch_bounds__(256)
void k_comb(const float* __restrict__ pw, const float* __restrict__ pb,
            float* __restrict__ out)
{
    int gw = (blockIdx.x * blockDim.x + threadIdx.x) >> 5;
    if (gw >= Nn) return;
    int lane = threadIdx.x & 31;
    const float pw0 = pw[2 * lane], pw1 = pw[2 * lane + 1];
    const float bias = pb[0];
    float ox = 0.f, oy = 0.f;
    #pragma unroll
    for (int k = 0; k <= KHOP; k++) {
        __half2 h = *reinterpret_cast<const __half2*>(
            &g_X[((size_t)k * Nn + gw) * OUTC + 2 * lane]);
        float2 v = __half22float2(h);
        float t = v.x * pw0 + v.y * pw1;
        #pragma unroll
        for (int o = 16; o; o >>= 1) t += __shfl_xor_sync(0xffffffffu, t, o);
        float s = 1.f / (1.f + expf(-(t + bias)));
        ox = fmaf(s, v.x, ox);
        oy = fmaf(s, v.y, oy);
    }
    reinterpret_cast<float2*>(out)[gw * 32 + lane] = make_float2(ox, oy);
}

// ---------------- launch ----------------
extern "C" void kernel_launch(void* const* d_in, const int* in_sizes, int n_in,
                              void* d_out, int out_size)
{
    const float* node_feat = (const float*)d_in[0];
    const int*   ei32      = (const int*)d_in[1];
    const float* W1        = (const float*)d_in[2];
    const float* b1        = (const float*)d_in[3];
    const float* W2        = (const float*)d_in[4];
    const float* b2        = (const float*)d_in[5];
    const float* pw        = (const float*)d_in[6];
    const float* pb        = (const float*)d_in[7];
    float*       out       = (float*)d_out;

    const int TB = 256;
    int gN = (Nn + TB - 1) / TB;
    int gE = (Ee + TB - 1) / TB;
    int gW = (Nn * 32 + TB - 1) / TB;
    int gP = (Nn + 1) / 2;

    const int SMEM0 = 4 * 20480 + 128 * STF * 4;          // 100352 B
    const int SMEM1 = 2 * (2 * 128 + 2 * 64) * ST * 2;    // 61440 B
    cudaFuncSetAttribute(k_mma0, cudaFuncAttributeMaxDynamicSharedMemorySize, SMEM0);
    cudaFuncSetAttribute(k_mma1, cudaFuncAttributeMaxDynamicSharedMemorySize, SMEM1);

    // ---- fork: CSR chain on g_hx.s2, MLP chain on the default stream ----
    cudaEventRecord(g_hx.ev_fork, 0);
    cudaStreamWaitEvent(g_hx.s2, g_hx.ev_fork, 0);

    // CSR chain (stream s2)
    k_detect<<<1, 1, 0, g_hx.s2>>>(ei32);
    k_zero_cnt<<<gN, TB, 0, g_hx.s2>>>();
    k_count<<<gE, TB, 0, g_hx.s2>>>(ei32);
    k_scan1<<<NB_SCAN, 1024, 0, g_hx.s2>>>();
    k_scan2<<<1, 1, 0, g_hx.s2>>>();
    k_scan3<<<NB_SCAN, 1024, 0, g_hx.s2>>>();
    k_fill<<<gE, TB, 0, g_hx.s2>>>(ei32);
    k_sortwarp<<<gW, TB, 0, g_hx.s2>>>();
    cudaEventRecord(g_hx.ev_join, g_hx.s2);

    // MLP chain (default stream)
    k_convW1<<<(HIDC * KP1 + TB - 1) / TB, TB>>>(W1);
    k_convW2<<<(OUTC * HIDC + TB - 1) / TB, TB>>>(W2);
    dim3 g1((Nn + 127) / 128, 2);
    k_mma0<<<g1, 256, SMEM0>>>(node_feat, b1, Nn);
    dim3 g2((Nn + 127) / 128, 1);
    k_mma1<<<g2, 256, SMEM1>>>(b2, Nn);

    // ---- join: props need both x_0 (default stream) and CSR (s2) ----
    cudaStreamWaitEvent(0, g_hx.ev_join, 0);

    // SpMV hops then fused combine
    for (int k = 1; k <= KHOP; k++)
        k_prop<<<gP, 64>>>(k);
    k_comb<<<gW, TB>>>(pw, pb, out);
}